// round 13
// baseline (speedup 1.0000x reference)
#include <cuda_runtime.h>
#include <cstdint>
#include <math.h>

// ---------------------------------------------------------------------------
// VGG-small 1w1a forward, batch 256.
// conv0 fp32 -> stats0(comp-fp32, exact fp32 boundary) -> pack0+packw ->
// [bconv popcount SCATTER (reg weights, single-pass acts) -> int stats ->
//  int pack] x5 -> bn+ht -> fc
// ---------------------------------------------------------------------------

__device__ __align__(16) float    g_A[33554432];   // conv0 fp32 / int16 NCHW
__device__ __align__(16) float    g_C[8388608];    // pooled int16 NCHW
__device__ __align__(16) uint32_t g_P[1048576];    // bitpacked act [n][y][x][NW]
__device__ __align__(16) uint32_t g_Wp[142848];    // bitpacked weights
__device__ float  g_fthr[512];
__device__ int    g_fsgn[512];
__device__ int    g_ithr[512];
__device__ int    g_isgn[512];
__device__ float  g_fsc[512];
__device__ float  g_fsf[512];

// ---------------- compensated fp32 helpers ---------------------------------
__device__ __forceinline__ void two_sum(float& s, float& c, float v) {
  float t = __fadd_rn(s, v);
  float z = __fsub_rn(t, s);
  float e = __fadd_rn(__fsub_rn(s, __fsub_rn(t, z)), __fsub_rn(v, z));
  s = t;
  c = __fadd_rn(c, e);
}

// ---------------- conv0: fp32 3->128, 32x32, pad 1 -------------------------
__global__ __launch_bounds__(256) void conv0_kernel(
    const float* __restrict__ x, const float* __restrict__ w,
    float* __restrict__ out) {
  __shared__ float sW[128 * 27];
  __shared__ float sX[3][3][34];
  int bx = blockIdx.x;
  int y = bx & 31, n = bx >> 5;
  int tid = threadIdx.x;
  for (int i = tid; i < 3456; i += 256) sW[i] = w[i];
  for (int i = tid; i < 3 * 3 * 34; i += 256) {
    int col = i % 34;
    int r = (i / 34) % 3;
    int ci = i / (34 * 3);
    int gy = y - 1 + r, gx = col - 1;
    float v = 0.f;
    if (gy >= 0 && gy < 32 && gx >= 0 && gx < 32)
      v = x[((n * 3 + ci) * 32 + gy) * 32 + gx];
    sX[ci][r][col] = v;
  }
  __syncthreads();
  int co = tid >> 1, xh = tid & 1, x0 = xh * 16;
  float wr[27];
#pragma unroll
  for (int ky = 0; ky < 3; ky++)
#pragma unroll
    for (int kx = 0; kx < 3; kx++)
#pragma unroll
      for (int ci = 0; ci < 3; ci++)
        wr[(ky * 3 + kx) * 3 + ci] = sW[((co * 3 + ci) * 3 + ky) * 3 + kx];
  float a[3][3][3];
#pragma unroll
  for (int r = 0; r < 3; r++)
#pragma unroll
    for (int ci = 0; ci < 3; ci++) {
      a[r][0][ci] = sX[ci][r][x0];
      a[r][1][ci] = sX[ci][r][x0 + 1];
    }
  float* obase = out + (((size_t)n * 128 + co) * 32 + y) * 32;
#pragma unroll
  for (int xi = 0; xi < 16; xi++) {
    int xc = x0 + xi;
#pragma unroll
    for (int r = 0; r < 3; r++)
#pragma unroll
      for (int ci = 0; ci < 3; ci++) a[r][2][ci] = sX[ci][r][xc + 2];
    float acc = 0.f;
#pragma unroll
    for (int ky = 0; ky < 3; ky++)
#pragma unroll
      for (int kx = 0; kx < 3; kx++)
#pragma unroll
        for (int ci = 0; ci < 3; ci++)
          acc = fmaf(a[ky][kx][ci], wr[(ky * 3 + kx) * 3 + ci], acc);
    obase[xc] = acc;
#pragma unroll
    for (int r = 0; r < 3; r++)
#pragma unroll
      for (int ci = 0; ci < 3; ci++) {
        a[r][0][ci] = a[r][1][ci];
        a[r][1][ci] = a[r][2][ci];
      }
  }
}

// ------- layer0 stats: one block per channel + exact fp32 boundary ---------
__global__ __launch_bounds__(256) void stats0_all(
    const float* __restrict__ x, const float* __restrict__ g,
    const float* __restrict__ b, float* __restrict__ fthr,
    int* __restrict__ fsgn) {
  int c = blockIdx.x;
  float s = 0.f, cs = 0.f, ss = 0.f, css = 0.f;
  for (int n = 0; n < 256; n++) {
    const float* p = x + ((size_t)n * 128 + c) * 1024;
    for (int i = threadIdx.x; i < 1024; i += 256) {
      float v = p[i];
      two_sum(s, cs, v);
      float v2 = __fmul_rn(v, v);
      float e2 = __fmaf_rn(v, v, -v2);
      two_sum(ss, css, v2);
      css = __fadd_rn(css, e2);
    }
  }
  __shared__ double sh1[256], sh2[256];
  sh1[threadIdx.x] = (double)s + (double)cs;
  sh2[threadIdx.x] = (double)ss + (double)css;
  __syncthreads();
  for (int o = 128; o > 0; o >>= 1) {
    if (threadIdx.x < o) {
      sh1[threadIdx.x] += sh1[threadIdx.x + o];
      sh2[threadIdx.x] += sh2[threadIdx.x + o];
    }
    __syncthreads();
  }
  if (threadIdx.x == 0) {
    double cnt = 256.0 * 1024.0;
    double mean = sh1[0] / cnt;
    double var = sh2[0] / cnt - mean * mean;
    double sc = (double)g[c] * rsqrt(var + 1e-5);
    double sf = (double)b[c] - mean * sc;
    if (sc > 0.0) {
      float v = (float)(-sf / sc);
      if (!isfinite(v)) v = 0.f;
      if (fma((double)v, sc, sf) >= 0.0) {
        for (int it = 0; it < 64; it++) {
          float d = nextafterf(v, -INFINITY);
          if (fma((double)d, sc, sf) >= 0.0) v = d; else break;
        }
      } else {
        for (int it = 0; it < 64; it++) {
          v = nextafterf(v, INFINITY);
          if (fma((double)v, sc, sf) >= 0.0) break;
        }
      }
      fthr[c] = v;
      fsgn[c] = 1;
    } else if (sc < 0.0) {
      float v = (float)(-sf / sc);
      if (!isfinite(v)) v = 0.f;
      if (fma((double)v, sc, sf) >= 0.0) {
        for (int it = 0; it < 64; it++) {
          float d = nextafterf(v, INFINITY);
          if (fma((double)d, sc, sf) >= 0.0) v = d; else break;
        }
      } else {
        for (int it = 0; it < 64; it++) {
          v = nextafterf(v, -INFINITY);
          if (fma((double)v, sc, sf) >= 0.0) break;
        }
      }
      fthr[c] = v;
      fsgn[c] = 0;
    } else {
      fthr[c] = (sf >= 0.0) ? -INFINITY : INFINITY;
      fsgn[c] = 1;
    }
  }
}

// ------- fused: pack0 act bitpack + weight bitpack --------------------------
__global__ __launch_bounds__(256) void pack0_packw_kernel(
    const float* __restrict__ x, const float* __restrict__ fthr,
    const int* __restrict__ fsgn, uint32_t* __restrict__ apk,
    const float* __restrict__ w1, const float* __restrict__ w2,
    const float* __restrict__ w3, const float* __restrict__ w4,
    const float* __restrict__ w5, uint32_t* __restrict__ wpk) {
  const int R0 = 4096;
  int tid = threadIdx.x;
  int bx = blockIdx.x;
  if (bx < R0) {
    int gt = bx * 256 + tid;
    int lane = gt & 31;
    int gw = gt >> 5;
    int wrd = gw & 3;
    int pixel = (gw >> 2) * 32 + lane;
    int n = pixel >> 10, hw = pixel & 1023;
    const float* base = x + ((size_t)(n * 128 + wrd * 32)) * 1024 + hw;
    const float* tp = fthr + wrd * 32;
    const int* sp = fsgn + wrd * 32;
    uint32_t bits = 0;
#pragma unroll 8
    for (int k = 0; k < 32; k++) {
      float v = base[(size_t)k * 1024];
      bool bit = sp[k] ? (v >= tp[k]) : (v <= tp[k]);
      bits |= (bit ? 1u : 0u) << k;
    }
    apk[(size_t)pixel * 4 + wrd] = bits;
  } else {
    int idx = (bx - R0) * 256 + tid;
    if (idx >= 142848) return;
    const float* w;
    int Ci, l;
    if (idx < 4608) { w = w1; Ci = 128; l = idx; }
    else if (idx < 13824) { w = w2; Ci = 128; l = idx - 4608; }
    else if (idx < 32256) { w = w3; Ci = 256; l = idx - 13824; }
    else if (idx < 69120) { w = w4; Ci = 256; l = idx - 32256; }
    else { w = w5; Ci = 512; l = idx - 69120; }
    int NW = Ci >> 5;
    int wrd = l % NW;
    int t = l / NW;
    int tap = t % 9;
    int co = t / 9;
    uint32_t bits = 0;
#pragma unroll 8
    for (int k = 0; k < 32; k++) {
      float v = w[((size_t)co * Ci + (wrd * 32 + k)) * 9 + tap];
      bits |= (v >= 0.f ? 1u : 0u) << k;
    }
    wpk[idx] = bits;
  }
}

// ------- binary conv 3x3 pad 1: SCATTER (reg weights, 1-pass acts) ---------
__device__ __forceinline__ int popc4(uint4 a, uint4 b) {
  return __popc(a.x ^ b.x) + __popc(a.y ^ b.y) +
         __popc(a.z ^ b.z) + __popc(a.w ^ b.w);
}

template <int CO, int CO_G, int H, int W, int NW, int SPLIT, int YT, int XT,
          bool POOL>
__global__ __launch_bounds__(CO_G* SPLIT*(W / XT), 2) void bconv6_kernel(
    const uint32_t* __restrict__ apk, const uint32_t* __restrict__ wpk,
    short* __restrict__ out) {
  constexpr int NTH = CO_G * SPLIT * (W / XT);
  constexpr int CGRP = CO / CO_G;
  __shared__ uint32_t sW[CO_G * 9 * NW];
  __shared__ uint32_t sA[(YT + 2) * W * NW];
  int bx = blockIdx.x;
  int cg = bx % CGRP;
  int yg = (bx / CGRP) % (H / YT);
  int n = bx / (CGRP * (H / YT));
  int tid = threadIdx.x;
  const uint4* wsrc =
      reinterpret_cast<const uint4*>(wpk + (size_t)cg * CO_G * 9 * NW);
  for (int i = tid; i < CO_G * 9 * NW / 4; i += NTH)
    reinterpret_cast<uint4*>(sW)[i] = wsrc[i];
  int ybase = yg * YT;
  constexpr int RW4 = W * NW / 4;
  for (int i = tid; i < (YT + 2) * RW4; i += NTH) {
    int r = i / RW4;
    int gy = ybase - 1 + r;
    uint4 v = make_uint4(0u, 0u, 0u, 0u);
    if (gy >= 0 && gy < H)
      v = reinterpret_cast<const uint4*>(
          apk + ((size_t)(n * H + gy) * W) * NW)[i % RW4];
    reinterpret_cast<uint4*>(sA)[i] = v;
  }
  __syncthreads();
  int slice = tid % SPLIT;
  int t2 = tid / SPLIT;
  int xg = t2 % (W / XT);
  int co_l = t2 / (W / XT);
  int x0 = xg * XT;
  // weights resident in registers for the whole kernel (9 LDS.128 total)
  uint4 wt[9];
#pragma unroll
  for (int t = 0; t < 9; t++)
    wt[t] = *reinterpret_cast<const uint4*>(
        &sW[(co_l * 9 + t) * NW + slice * 4]);
  int co = cg * CO_G + co_l;
  int pmax[XT / 2];
  int tmpv = 0;
#pragma unroll
  for (int ry = 0; ry < YT; ry++) {
    int y = ybase + ry;
    int rv0 = (y > 0) ? 1 : 0;
    int rv2 = (y < H - 1) ? 1 : 0;
    int nrows = 1 + rv0 + rv2;
    int cnt[XT];
#pragma unroll
    for (int xi = 0; xi < XT; xi++) cnt[xi] = 0;
    // scatter: each act column loaded once, feeds up to 3 outputs from regs
#pragma unroll
    for (int rr = 0; rr < 3; rr++) {
      int rvalid = (rr == 0) ? rv0 : ((rr == 2) ? rv2 : 1);
      if (rvalid) {
        const uint32_t* row = &sA[(ry + rr) * W * NW + slice * 4];
#pragma unroll
        for (int j = 0; j < XT + 2; j++) {
          int p = x0 + j - 1;  // act column
          if (p >= 0 && p < W) {
            uint4 a = *reinterpret_cast<const uint4*>(&row[p * NW]);
            if (j >= 2) cnt[j - 2] += popc4(a, wt[rr * 3 + 2]);
            if (j >= 1 && j - 1 < XT) cnt[j - 1] += popc4(a, wt[rr * 3 + 1]);
            if (j < XT) cnt[j] += popc4(a, wt[rr * 3 + 0]);
          }
        }
      }
    }
    // epilogue for this output row
#pragma unroll
    for (int xi = 0; xi < XT; xi++) {
      int xc = x0 + xi;
      int cl = (xc > 0) ? 1 : 0;
      int cr = (xc < W - 1) ? 1 : 0;
      int c = cnt[xi];
#pragma unroll
      for (int o = 1; o < SPLIT; o <<= 1)
        c += __shfl_xor_sync(0xffffffffu, c, o);
      int ncols = 1 + cl + cr;
      int val = nrows * ncols * 32 * NW - 2 * c;
      if (POOL) {
        if ((xi & 1) == 0) {
          tmpv = val;
        } else {
          int m2 = max(tmpv, val);
          if ((ry & 1) == 0) {
            pmax[xi >> 1] = m2;
          } else {
            int m = max(pmax[xi >> 1], m2);
            if (slice == 0)
              out[(((size_t)n * CO + co) * (H / 2) + (y >> 1)) * (W / 2) +
                  (xc >> 1)] = (short)m;
          }
        }
      } else {
        if (slice == 0)
          out[(((size_t)n * CO + co) * H + y) * W + xc] = (short)val;
      }
    }
  }
}

// -------- binary-layer stats: exact int64 accumulation ---------------------
__global__ __launch_bounds__(256) void stats_int_kernel(
    const short* __restrict__ x, const float* __restrict__ g,
    const float* __restrict__ b, float* __restrict__ fsc,
    float* __restrict__ fsf, int* __restrict__ thr, int* __restrict__ sgn,
    int N, int C, int HW) {
  int c = blockIdx.x;
  long long s = 0, ss = 0;
  for (int n = 0; n < N; n++) {
    const short* p = x + ((size_t)n * C + c) * HW;
    for (int i = threadIdx.x; i < HW; i += 256) {
      int v = p[i];
      s += v;
      ss += (long long)(v * v);
    }
  }
  __shared__ long long sh1[256], sh2[256];
  sh1[threadIdx.x] = s;
  sh2[threadIdx.x] = ss;
  __syncthreads();
  for (int o = 128; o > 0; o >>= 1) {
    if (threadIdx.x < o) {
      sh1[threadIdx.x] += sh1[threadIdx.x + o];
      sh2[threadIdx.x] += sh2[threadIdx.x + o];
    }
    __syncthreads();
  }
  if (threadIdx.x == 0) {
    double cnt = (double)N * (double)HW;
    double mean = (double)sh1[0] / cnt;
    double var = (double)sh2[0] / cnt - mean * mean;
    double sc = (double)g[c] * rsqrt(var + 1e-5);
    double sf = (double)b[c] - mean * sc;
    fsc[c] = (float)sc;
    fsf[c] = (float)sf;
    double T = -sf / sc;
    if (sc > 0.0) {
      thr[c] = (int)ceil(T);
      sgn[c] = 1;
    } else {
      thr[c] = (int)floor(T);
      sgn[c] = 0;
    }
  }
}

// -------- binary-layer pack: pure integer predicate ------------------------
__global__ __launch_bounds__(256) void pack_int_kernel(
    const short* __restrict__ x, const int* __restrict__ thr,
    const int* __restrict__ sgn, uint32_t* __restrict__ apk,
    int C, int HW, int NW) {
  int gt = blockIdx.x * 256 + threadIdx.x;
  int lane = gt & 31;
  int gw = gt >> 5;
  int wrd = gw % NW;
  int chunk = gw / NW;
  int pixel = chunk * 32 + lane;
  int n = pixel / HW, hw = pixel % HW;
  const short* base = x + ((size_t)n * C + wrd * 32) * HW + hw;
  const int* tp = thr + wrd * 32;
  const int* sp = sgn + wrd * 32;
  uint32_t bits = 0;
#pragma unroll 8
  for (int k = 0; k < 32; k++) {
    int v = base[(size_t)k * HW];
    bool bit = sp[k] ? (v >= tp[k]) : (v <= tp[k]);
    bits |= (bit ? 1u : 0u) << k;
  }
  apk[(size_t)pixel * NW + wrd] = bits;
}

// ------------- bn + hardtanh (fp32 continuous path) ------------------------
__global__ __launch_bounds__(256) void bn_ht_kernel(
    const short* __restrict__ in, const float* __restrict__ fsc,
    const float* __restrict__ fsf, float* __restrict__ out,
    int C, int HW, int total) {
  int idx = blockIdx.x * 256 + threadIdx.x;
  if (idx >= total) return;
  int c = (idx / HW) % C;
  float z = fmaf((float)in[idx], fsc[c], fsf[c]);
  out[idx] = fminf(1.f, fmaxf(-1.f, z));
}

// ----- FC: [256,8192] @ [10,8192]^T + b (TwoProd+Neumaier fp32) ------------
__global__ __launch_bounds__(256) void fc_kernel(
    const float* __restrict__ h, const float* __restrict__ wfc,
    const float* __restrict__ bfc, float* __restrict__ out) {
  int gtid = blockIdx.x * blockDim.x + threadIdx.x;
  int warp = gtid >> 5;
  int lane = gtid & 31;
  if (warp >= 256 * 10) return;
  int n = warp / 10, k = warp % 10;
  const float* hp = h + (size_t)n * 8192;
  const float* wp = wfc + (size_t)k * 8192;
  float s = 0.f, c = 0.f;
  for (int j = lane; j < 8192; j += 32) {
    float a = hp[j], b = wp[j];
    float p = __fmul_rn(a, b);
    float e = __fmaf_rn(a, b, -p);
    two_sum(s, c, p);
    c = __fadd_rn(c, e);
  }
  double d = (double)s + (double)c;
#pragma unroll
  for (int o = 16; o > 0; o >>= 1) d += __shfl_xor_sync(0xFFFFFFFFu, d, o);
  if (lane == 0) out[n * 10 + k] = (float)(d + (double)bfc[k]);
}

// ---------------------------------------------------------------------------
static inline int cdiv(int a, int b) { return (a + b - 1) / b; }

extern "C" void kernel_launch(void* const* d_in, const int* in_sizes, int n_in,
                              void* d_out, int out_size) {
  const float* x   = (const float*)d_in[0];
  const float* w0_ = (const float*)d_in[1];
  const float* g0  = (const float*)d_in[2];
  const float* b0  = (const float*)d_in[3];
  const float* wc1 = (const float*)d_in[4];
  const float* g1  = (const float*)d_in[5];
  const float* b1  = (const float*)d_in[6];
  const float* wc2 = (const float*)d_in[7];
  const float* g2  = (const float*)d_in[8];
  const float* b2  = (const float*)d_in[9];
  const float* wc3 = (const float*)d_in[10];
  const float* g3  = (const float*)d_in[11];
  const float* b3  = (const float*)d_in[12];
  const float* wc4 = (const float*)d_in[13];
  const float* g4  = (const float*)d_in[14];
  const float* b4  = (const float*)d_in[15];
  const float* wc5 = (const float*)d_in[16];
  const float* g5  = (const float*)d_in[17];
  const float* b5  = (const float*)d_in[18];
  const float* wfc = (const float*)d_in[19];
  const float* bfc = (const float*)d_in[20];
  float* out = (float*)d_out;

  float *A, *Cb, *fsc, *fsf, *fthr;
  uint32_t *P, *Wp;
  int *thr, *sgn, *fsgn;
  cudaGetSymbolAddress((void**)&A, g_A);
  cudaGetSymbolAddress((void**)&Cb, g_C);
  cudaGetSymbolAddress((void**)&P, g_P);
  cudaGetSymbolAddress((void**)&Wp, g_Wp);
  cudaGetSymbolAddress((void**)&fthr, g_fthr);
  cudaGetSymbolAddress((void**)&fsgn, g_fsgn);
  cudaGetSymbolAddress((void**)&thr, g_ithr);
  cudaGetSymbolAddress((void**)&sgn, g_isgn);
  cudaGetSymbolAddress((void**)&fsc, g_fsc);
  cudaGetSymbolAddress((void**)&fsf, g_fsf);
  short* As = (short*)A;
  short* Cs = (short*)Cb;
  float* hbuf = (float*)A;

  const int N = 256;
  const int TB = 256;

  // 0: conv0; 1: stats0; 2: pack0+packw; 3: bconv L1 (profiled slot)
  conv0_kernel<<<N * 32, TB>>>(x, w0_, A);
  stats0_all<<<128, TB>>>(A, g0, b0, fthr, fsgn);
  pack0_packw_kernel<<<4096 + 558, TB>>>(A, fthr, fsgn, P, wc1, wc2, wc3,
                                         wc4, wc5, Wp);

  // L1: 128->128 @32 +pool -> Cs
  bconv6_kernel<128, 128, 32, 32, 4, 1, 4, 16, true>
      <<<N * 8, TB>>>(P, Wp + 0, Cs);
  stats_int_kernel<<<128, TB>>>(Cs, g1, b1, fsc, fsf, thr, sgn, N, 128, 256);
  pack_int_kernel<<<N * 256 * 4 / TB, TB>>>(Cs, thr, sgn, P, 128, 256, 4);

  // L2: 128->256 @16 -> As
  bconv6_kernel<256, 256, 16, 16, 4, 1, 4, 16, false>
      <<<N * 4, TB>>>(P, Wp + 4608, As);
  stats_int_kernel<<<256, TB>>>(As, g2, b2, fsc, fsf, thr, sgn, N, 256, 256);
  pack_int_kernel<<<N * 256 * 8 / TB, TB>>>(As, thr, sgn, P, 256, 256, 8);

  // L3: 256->256 @16 +pool -> Cs
  bconv6_kernel<256, 128, 16, 16, 8, 2, 4, 16, true>
      <<<N * 8, TB>>>(P, Wp + 13824, Cs);
  stats_int_kernel<<<256, TB>>>(Cs, g3, b3, fsc, fsf, thr, sgn, N, 256, 64);
  pack_int_kernel<<<N * 64 * 8 / TB, TB>>>(Cs, thr, sgn, P, 256, 64, 8);

  // L4: 256->512 @8 -> As
  bconv6_kernel<512, 128, 8, 8, 8, 2, 4, 8, false>
      <<<N * 8, TB>>>(P, Wp + 32256, As);
  stats_int_kernel<<<512, TB>>>(As, g4, b4, fsc, fsf, thr, sgn, N, 512, 64);
  pack_int_kernel<<<N * 64 * 16 / TB, TB>>>(As, thr, sgn, P, 512, 64, 16);

  // L5: 512->512 @8 +pool -> Cs
  bconv6_kernel<512, 64, 8, 8, 16, 4, 4, 8, true>
      <<<N * 16, TB>>>(P, Wp + 69120, Cs);
  stats_int_kernel<<<512, TB>>>(Cs, g5, b5, fsc, fsf, thr, sgn, N, 512, 16);

  // bn5 + hardtanh -> hbuf, then FC
  bn_ht_kernel<<<cdiv(2097152, TB), TB>>>(Cs, fsc, fsf, hbuf, 512, 16,
                                          2097152);
  fc_kernel<<<cdiv(N * 10 * 32, TB), TB>>>(hbuf, wfc, bfc, out);
}

// round 14
// speedup vs baseline: 1.9991x; 1.9991x over previous
#include <cuda_runtime.h>
#include <cstdint>
#include <math.h>

// ---------------------------------------------------------------------------
// VGG-small 1w1a forward, batch 256.  (R5 bconv verbatim + parallel stats)
// conv0 fp32 -> stats0 (2-stage comp-fp32, exact fp32 boundary) ->
// pack0+packw -> [bconv popcount (sliding window, reg weights, fused pool)
// -> 2-stage int64 stats -> int pack] x5 -> bn+ht -> fc
// ---------------------------------------------------------------------------

__device__ __align__(16) float    g_A[33554432];   // conv0 fp32 / int16 NCHW
__device__ __align__(16) float    g_C[8388608];    // pooled int16 NCHW
__device__ __align__(16) uint32_t g_P[1048576];    // bitpacked act [n][y][x][NW]
__device__ __align__(16) uint32_t g_Wp[142848];    // bitpacked weights
__device__ double    g_part[8192];                 // stats0 partials
__device__ long long g_pll[16384];                 // int stats partials
__device__ float  g_fthr[512];
__device__ int    g_fsgn[512];
__device__ int    g_ithr[512];
__device__ int    g_isgn[512];
__device__ float  g_fsc[512];
__device__ float  g_fsf[512];

// ---------------- compensated fp32 helpers ---------------------------------
__device__ __forceinline__ void two_sum(float& s, float& c, float v) {
  float t = __fadd_rn(s, v);
  float z = __fsub_rn(t, s);
  float e = __fadd_rn(__fsub_rn(s, __fsub_rn(t, z)), __fsub_rn(v, z));
  s = t;
  c = __fadd_rn(c, e);
}

// ---------------- conv0: fp32 3->128, 32x32, pad 1 -------------------------
__global__ __launch_bounds__(256) void conv0_kernel(
    const float* __restrict__ x, const float* __restrict__ w,
    float* __restrict__ out) {
  __shared__ float sW[128 * 27];
  __shared__ float sX[3][3][34];
  int bx = blockIdx.x;
  int y = bx & 31, n = bx >> 5;
  int tid = threadIdx.x;
  for (int i = tid; i < 3456; i += 256) sW[i] = w[i];
  for (int i = tid; i < 3 * 3 * 34; i += 256) {
    int col = i % 34;
    int r = (i / 34) % 3;
    int ci = i / (34 * 3);
    int gy = y - 1 + r, gx = col - 1;
    float v = 0.f;
    if (gy >= 0 && gy < 32 && gx >= 0 && gx < 32)
      v = x[((n * 3 + ci) * 32 + gy) * 32 + gx];
    sX[ci][r][col] = v;
  }
  __syncthreads();
  int co = tid >> 1, xh = tid & 1, x0 = xh * 16;
  float wr[27];
#pragma unroll
  for (int ky = 0; ky < 3; ky++)
#pragma unroll
    for (int kx = 0; kx < 3; kx++)
#pragma unroll
      for (int ci = 0; ci < 3; ci++)
        wr[(ky * 3 + kx) * 3 + ci] = sW[((co * 3 + ci) * 3 + ky) * 3 + kx];
  float a[3][3][3];
#pragma unroll
  for (int r = 0; r < 3; r++)
#pragma unroll
    for (int ci = 0; ci < 3; ci++) {
      a[r][0][ci] = sX[ci][r][x0];
      a[r][1][ci] = sX[ci][r][x0 + 1];
    }
  float* obase = out + (((size_t)n * 128 + co) * 32 + y) * 32;
#pragma unroll
  for (int xi = 0; xi < 16; xi++) {
    int xc = x0 + xi;
#pragma unroll
    for (int r = 0; r < 3; r++)
#pragma unroll
      for (int ci = 0; ci < 3; ci++) a[r][2][ci] = sX[ci][r][xc + 2];
    float acc = 0.f;
#pragma unroll
    for (int ky = 0; ky < 3; ky++)
#pragma unroll
      for (int kx = 0; kx < 3; kx++)
#pragma unroll
        for (int ci = 0; ci < 3; ci++)
          acc = fmaf(a[ky][kx][ci], wr[(ky * 3 + kx) * 3 + ci], acc);
    obase[xc] = acc;
#pragma unroll
    for (int r = 0; r < 3; r++)
#pragma unroll
      for (int ci = 0; ci < 3; ci++) {
        a[r][0][ci] = a[r][1][ci];
        a[r][1][ci] = a[r][2][ci];
      }
  }
}

// ------- layer0 stats: 2-stage, comp-fp32 partials, fp64 combine -----------
__global__ __launch_bounds__(256) void stats0_partial(
    const float* __restrict__ x, double* __restrict__ part) {
  int c = blockIdx.x, ch = blockIdx.y;
  float s = 0.f, cs = 0.f, ss = 0.f, css = 0.f;
  for (int n = ch * 32; n < (ch + 1) * 32; n++) {
    const float* p = x + ((size_t)n * 128 + c) * 1024;
    for (int i = threadIdx.x; i < 1024; i += 256) {
      float v = p[i];
      two_sum(s, cs, v);
      float v2 = __fmul_rn(v, v);
      float e2 = __fmaf_rn(v, v, -v2);
      two_sum(ss, css, v2);
      css = __fadd_rn(css, e2);
    }
  }
  __shared__ double sh1[256], sh2[256];
  sh1[threadIdx.x] = (double)s + (double)cs;
  sh2[threadIdx.x] = (double)ss + (double)css;
  __syncthreads();
  for (int o = 128; o > 0; o >>= 1) {
    if (threadIdx.x < o) {
      sh1[threadIdx.x] += sh1[threadIdx.x + o];
      sh2[threadIdx.x] += sh2[threadIdx.x + o];
    }
    __syncthreads();
  }
  if (threadIdx.x == 0) {
    part[c * 8 + ch] = sh1[0];
    part[4096 + c * 8 + ch] = sh2[0];
  }
}

__global__ void stats0_fin(const double* __restrict__ part,
                           const float* __restrict__ g,
                           const float* __restrict__ b,
                           float* __restrict__ fthr, int* __restrict__ fsgn) {
  int c = blockIdx.x * blockDim.x + threadIdx.x;
  if (c >= 128) return;
  double S = 0.0, SS = 0.0;
  for (int ch = 0; ch < 8; ch++) {
    S += part[c * 8 + ch];
    SS += part[4096 + c * 8 + ch];
  }
  double cnt = 256.0 * 1024.0;
  double mean = S / cnt;
  double var = SS / cnt - mean * mean;
  double sc = (double)g[c] * rsqrt(var + 1e-5);
  double sf = (double)b[c] - mean * sc;
  if (sc > 0.0) {
    float v = (float)(-sf / sc);
    if (!isfinite(v)) v = 0.f;
    if (fma((double)v, sc, sf) >= 0.0) {
      for (int it = 0; it < 64; it++) {
        float d = nextafterf(v, -INFINITY);
        if (fma((double)d, sc, sf) >= 0.0) v = d; else break;
      }
    } else {
      for (int it = 0; it < 64; it++) {
        v = nextafterf(v, INFINITY);
        if (fma((double)v, sc, sf) >= 0.0) break;
      }
    }
    fthr[c] = v;
    fsgn[c] = 1;
  } else if (sc < 0.0) {
    float v = (float)(-sf / sc);
    if (!isfinite(v)) v = 0.f;
    if (fma((double)v, sc, sf) >= 0.0) {
      for (int it = 0; it < 64; it++) {
        float d = nextafterf(v, INFINITY);
        if (fma((double)d, sc, sf) >= 0.0) v = d; else break;
      }
    } else {
      for (int it = 0; it < 64; it++) {
        v = nextafterf(v, -INFINITY);
        if (fma((double)v, sc, sf) >= 0.0) break;
      }
    }
    fthr[c] = v;
    fsgn[c] = 0;
  } else {
    fthr[c] = (sf >= 0.0) ? -INFINITY : INFINITY;
    fsgn[c] = 1;
  }
}

// ------- fused: pack0 act bitpack + weight bitpack --------------------------
__global__ __launch_bounds__(256) void pack0_packw_kernel(
    const float* __restrict__ x, const float* __restrict__ fthr,
    const int* __restrict__ fsgn, uint32_t* __restrict__ apk,
    const float* __restrict__ w1, const float* __restrict__ w2,
    const float* __restrict__ w3, const float* __restrict__ w4,
    const float* __restrict__ w5, uint32_t* __restrict__ wpk) {
  const int R0 = 4096;
  int tid = threadIdx.x;
  int bx = blockIdx.x;
  if (bx < R0) {
    int gt = bx * 256 + tid;
    int lane = gt & 31;
    int gw = gt >> 5;
    int wrd = gw & 3;
    int pixel = (gw >> 2) * 32 + lane;
    int n = pixel >> 10, hw = pixel & 1023;
    const float* base = x + ((size_t)(n * 128 + wrd * 32)) * 1024 + hw;
    const float* tp = fthr + wrd * 32;
    const int* sp = fsgn + wrd * 32;
    uint32_t bits = 0;
#pragma unroll 8
    for (int k = 0; k < 32; k++) {
      float v = base[(size_t)k * 1024];
      bool bit = sp[k] ? (v >= tp[k]) : (v <= tp[k]);
      bits |= (bit ? 1u : 0u) << k;
    }
    apk[(size_t)pixel * 4 + wrd] = bits;
  } else {
    int idx = (bx - R0) * 256 + tid;
    if (idx >= 142848) return;
    const float* w;
    int Ci, l;
    if (idx < 4608) { w = w1; Ci = 128; l = idx; }
    else if (idx < 13824) { w = w2; Ci = 128; l = idx - 4608; }
    else if (idx < 32256) { w = w3; Ci = 256; l = idx - 13824; }
    else if (idx < 69120) { w = w4; Ci = 256; l = idx - 32256; }
    else { w = w5; Ci = 512; l = idx - 69120; }
    int NW = Ci >> 5;
    int wrd = l % NW;
    int t = l / NW;
    int tap = t % 9;
    int co = t / 9;
    uint32_t bits = 0;
#pragma unroll 8
    for (int k = 0; k < 32; k++) {
      float v = w[((size_t)co * Ci + (wrd * 32 + k)) * 9 + tap];
      bits |= (v >= 0.f ? 1u : 0u) << k;
    }
    wpk[idx] = bits;
  }
}

// ---- binary conv 3x3 pad 1 (R5 verbatim: sliding window, reg weights) -----
__device__ __forceinline__ int popc4(uint4 a, uint4 b) {
  return __popc(a.x ^ b.x) + __popc(a.y ^ b.y) +
         __popc(a.z ^ b.z) + __popc(a.w ^ b.w);
}

template <int CO, int CO_G, int H, int W, int NW, int SPLIT, int YT, int XT,
          bool POOL>
__global__ __launch_bounds__(CO_G* SPLIT*(W / XT)) void bconv2_kernel(
    const uint32_t* __restrict__ apk, const uint32_t* __restrict__ wpk,
    short* __restrict__ out) {
  constexpr int NTH = CO_G * SPLIT * (W / XT);
  constexpr int CGRP = CO / CO_G;
  __shared__ uint32_t sW[CO_G * 9 * NW];
  __shared__ uint32_t sA[(YT + 2) * W * NW];
  int bx = blockIdx.x;
  int cg = bx % CGRP;
  int yg = (bx / CGRP) % (H / YT);
  int n = bx / (CGRP * (H / YT));
  int tid = threadIdx.x;
  const uint4* wsrc =
      reinterpret_cast<const uint4*>(wpk + (size_t)cg * CO_G * 9 * NW);
  for (int i = tid; i < CO_G * 9 * NW / 4; i += NTH)
    reinterpret_cast<uint4*>(sW)[i] = wsrc[i];
  int ybase = yg * YT;
  constexpr int RW4 = W * NW / 4;
  for (int i = tid; i < (YT + 2) * RW4; i += NTH) {
    int r = i / RW4;
    int gy = ybase - 1 + r;
    uint4 v = make_uint4(0u, 0u, 0u, 0u);
    if (gy >= 0 && gy < H)
      v = reinterpret_cast<const uint4*>(
          apk + ((size_t)(n * H + gy) * W) * NW)[i % RW4];
    reinterpret_cast<uint4*>(sA)[i] = v;
  }
  __syncthreads();
  int slice = tid % SPLIT;
  int t2 = tid / SPLIT;
  int xg = t2 % (W / XT);
  int co_l = t2 / (W / XT);
  int x0 = xg * XT;
  uint4 wt[9];
#pragma unroll
  for (int t = 0; t < 9; t++)
    wt[t] = *reinterpret_cast<const uint4*>(
        &sW[(co_l * 9 + t) * NW + slice * 4]);
  int co = cg * CO_G + co_l;
  int pmax[XT / 2];
  int tmpv = 0;
#pragma unroll
  for (int ry = 0; ry < YT; ry++) {
    int y = ybase + ry;
    int rv0 = (y > 0) ? 1 : 0;
    int rv2 = (y < H - 1) ? 1 : 0;
    int nrows = 1 + rv0 + rv2;
    uint4 aL[3], aM[3], aR[3];
#pragma unroll
    for (int rr = 0; rr < 3; rr++) {
      aM[rr] = *reinterpret_cast<const uint4*>(
          &sA[((ry + rr) * W + x0) * NW + slice * 4]);
      aL[rr] = (x0 > 0)
                   ? *reinterpret_cast<const uint4*>(
                         &sA[((ry + rr) * W + x0 - 1) * NW + slice * 4])
                   : make_uint4(0u, 0u, 0u, 0u);
    }
#pragma unroll
    for (int xi = 0; xi < XT; xi++) {
      int xc = x0 + xi;
      int cl = (xc > 0) ? 1 : 0;
      int cr = (xc < W - 1) ? 1 : 0;
#pragma unroll
      for (int rr = 0; rr < 3; rr++)
        aR[rr] = cr ? *reinterpret_cast<const uint4*>(
                          &sA[((ry + rr) * W + xc + 1) * NW + slice * 4])
                    : make_uint4(0u, 0u, 0u, 0u);
      int cnt = 0;
#pragma unroll
      for (int rr = 0; rr < 3; rr++) {
        int rvalid = (rr == 0) ? rv0 : ((rr == 2) ? rv2 : 1);
        if (rvalid) {
          if (cl) cnt += popc4(aL[rr], wt[rr * 3 + 0]);
          cnt += popc4(aM[rr], wt[rr * 3 + 1]);
          if (cr) cnt += popc4(aR[rr], wt[rr * 3 + 2]);
        }
      }
#pragma unroll
      for (int o = 1; o < SPLIT; o <<= 1)
        cnt += __shfl_xor_sync(0xffffffffu, cnt, o);
      int ncols = 1 + cl + cr;
      int val = nrows * ncols * 32 * NW - 2 * cnt;
      if (POOL) {
        if ((xi & 1) == 0) {
          tmpv = val;
        } else {
          int m2 = max(tmpv, val);
          if ((ry & 1) == 0) {
            pmax[xi >> 1] = m2;
          } else {
            int m = max(pmax[xi >> 1], m2);
            if (slice == 0)
              out[(((size_t)n * CO + co) * (H / 2) + (y >> 1)) * (W / 2) +
                  (xc >> 1)] = (short)m;
          }
        }
      } else {
        if (slice == 0)
          out[(((size_t)n * CO + co) * H + y) * W + xc] = (short)val;
      }
#pragma unroll
      for (int rr = 0; rr < 3; rr++) {
        aL[rr] = aM[rr];
        aM[rr] = aR[rr];
      }
    }
  }
}

// ------- binary-layer stats: 2-stage exact int64 ---------------------------
__global__ __launch_bounds__(256) void statsi_partial(
    const short* __restrict__ x, long long* __restrict__ pll,
    int C, int HW) {
  int c = blockIdx.x, ch = blockIdx.y;
  long long s = 0, ss = 0;
  for (int n = ch * 32; n < (ch + 1) * 32; n++) {
    const short* p = x + ((size_t)n * C + c) * HW;
    for (int i = threadIdx.x; i < HW; i += 256) {
      int v = p[i];
      s += v;
      ss += (long long)(v * v);
    }
  }
  __shared__ long long sh1[256], sh2[256];
  sh1[threadIdx.x] = s;
  sh2[threadIdx.x] = ss;
  __syncthreads();
  for (int o = 128; o > 0; o >>= 1) {
    if (threadIdx.x < o) {
      sh1[threadIdx.x] += sh1[threadIdx.x + o];
      sh2[threadIdx.x] += sh2[threadIdx.x + o];
    }
    __syncthreads();
  }
  if (threadIdx.x == 0) {
    pll[c * 8 + ch] = sh1[0];
    pll[8192 + c * 8 + ch] = sh2[0];
  }
}

__global__ void statsi_fin(const long long* __restrict__ pll,
                           const float* __restrict__ g,
                           const float* __restrict__ b,
                           float* __restrict__ fsc, float* __restrict__ fsf,
                           int* __restrict__ thr, int* __restrict__ sgn,
                           int C, double cnt) {
  int c = blockIdx.x * blockDim.x + threadIdx.x;
  if (c >= C) return;
  long long S = 0, SS = 0;
  for (int ch = 0; ch < 8; ch++) {
    S += pll[c * 8 + ch];
    SS += pll[8192 + c * 8 + ch];
  }
  double mean = (double)S / cnt;
  double var = (double)SS / cnt - mean * mean;
  double sc = (double)g[c] * rsqrt(var + 1e-5);
  double sf = (double)b[c] - mean * sc;
  fsc[c] = (float)sc;
  fsf[c] = (float)sf;
  double T = -sf / sc;
  if (sc > 0.0) {
    thr[c] = (int)ceil(T);
    sgn[c] = 1;
  } else {
    thr[c] = (int)floor(T);
    sgn[c] = 0;
  }
}

// -------- binary-layer pack: pure integer predicate ------------------------
__global__ __launch_bounds__(256) void pack_int_kernel(
    const short* __restrict__ x, const int* __restrict__ thr,
    const int* __restrict__ sgn, uint32_t* __restrict__ apk,
    int C, int HW, int NW) {
  int gt = blockIdx.x * 256 + threadIdx.x;
  int lane = gt & 31;
  int gw = gt >> 5;
  int wrd = gw % NW;
  int chunk = gw / NW;
  int pixel = chunk * 32 + lane;
  int n = pixel / HW, hw = pixel % HW;
  const short* base = x + ((size_t)n * C + wrd * 32) * HW + hw;
  const int* tp = thr + wrd * 32;
  const int* sp = sgn + wrd * 32;
  uint32_t bits = 0;
#pragma unroll 8
  for (int k = 0; k < 32; k++) {
    int v = base[(size_t)k * HW];
    bool bit = sp[k] ? (v >= tp[k]) : (v <= tp[k]);
    bits |= (bit ? 1u : 0u) << k;
  }
  apk[(size_t)pixel * NW + wrd] = bits;
}

// ------------- bn + hardtanh (fp32 continuous path) ------------------------
__global__ __launch_bounds__(256) void bn_ht_kernel(
    const short* __restrict__ in, const float* __restrict__ fsc,
    const float* __restrict__ fsf, float* __restrict__ out,
    int C, int HW, int total) {
  int idx = blockIdx.x * 256 + threadIdx.x;
  if (idx >= total) return;
  int c = (idx / HW) % C;
  float z = fmaf((float)in[idx], fsc[c], fsf[c]);
  out[idx] = fminf(1.f, fmaxf(-1.f, z));
}

// ----- FC: [256,8192] @ [10,8192]^T + b (TwoProd+Neumaier fp32) ------------
__global__ __launch_bounds__(256) void fc_kernel(
    const float* __restrict__ h, const float* __restrict__ wfc,
    const float* __restrict__ bfc, float* __restrict__ out) {
  int gtid = blockIdx.x * blockDim.x + threadIdx.x;
  int warp = gtid >> 5;
  int lane = gtid & 31;
  if (warp >= 256 * 10) return;
  int n = warp / 10, k = warp % 10;
  const float* hp = h + (size_t)n * 8192;
  const float* wp = wfc + (size_t)k * 8192;
  float s = 0.f, c = 0.f;
  for (int j = lane; j < 8192; j += 32) {
    float a = hp[j], b = wp[j];
    float p = __fmul_rn(a, b);
    float e = __fmaf_rn(a, b, -p);
    two_sum(s, c, p);
    c = __fadd_rn(c, e);
  }
  double d = (double)s + (double)c;
#pragma unroll
  for (int o = 16; o > 0; o >>= 1) d += __shfl_xor_sync(0xFFFFFFFFu, d, o);
  if (lane == 0) out[n * 10 + k] = (float)(d + (double)bfc[k]);
}

// ---------------------------------------------------------------------------
static inline int cdiv(int a, int b) { return (a + b - 1) / b; }

extern "C" void kernel_launch(void* const* d_in, const int* in_sizes, int n_in,
                              void* d_out, int out_size) {
  const float* x   = (const float*)d_in[0];
  const float* w0_ = (const float*)d_in[1];
  const float* g0  = (const float*)d_in[2];
  const float* b0  = (const float*)d_in[3];
  const float* wc1 = (const float*)d_in[4];
  const float* g1  = (const float*)d_in[5];
  const float* b1  = (const float*)d_in[6];
  const float* wc2 = (const float*)d_in[7];
  const float* g2  = (const float*)d_in[8];
  const float* b2  = (const float*)d_in[9];
  const float* wc3 = (const float*)d_in[10];
  const float* g3  = (const float*)d_in[11];
  const float* b3  = (const float*)d_in[12];
  const float* wc4 = (const float*)d_in[13];
  const float* g4  = (const float*)d_in[14];
  const float* b4  = (const float*)d_in[15];
  const float* wc5 = (const float*)d_in[16];
  const float* g5  = (const float*)d_in[17];
  const float* b5  = (const float*)d_in[18];
  const float* wfc = (const float*)d_in[19];
  const float* bfc = (const float*)d_in[20];
  float* out = (float*)d_out;

  float *A, *Cb, *fsc, *fsf, *fthr;
  uint32_t *P, *Wp;
  double* part;
  long long* pll;
  int *thr, *sgn, *fsgn;
  cudaGetSymbolAddress((void**)&A, g_A);
  cudaGetSymbolAddress((void**)&Cb, g_C);
  cudaGetSymbolAddress((void**)&P, g_P);
  cudaGetSymbolAddress((void**)&Wp, g_Wp);
  cudaGetSymbolAddress((void**)&part, g_part);
  cudaGetSymbolAddress((void**)&pll, g_pll);
  cudaGetSymbolAddress((void**)&fthr, g_fthr);
  cudaGetSymbolAddress((void**)&fsgn, g_fsgn);
  cudaGetSymbolAddress((void**)&thr, g_ithr);
  cudaGetSymbolAddress((void**)&sgn, g_isgn);
  cudaGetSymbolAddress((void**)&fsc, g_fsc);
  cudaGetSymbolAddress((void**)&fsf, g_fsf);
  short* As = (short*)A;
  short* Cs = (short*)Cb;
  float* hbuf = (float*)A;

  const int N = 256;
  const int TB = 256;

  // 0: conv0; 1: stats0_partial; 2: stats0_fin; 3: pack0+packw;
  // 4: bconv L1 ... (ncu -s 5 lands within the bconv/stats block)
  conv0_kernel<<<N * 32, TB>>>(x, w0_, A);
  stats0_partial<<<dim3(128, 8), TB>>>(A, part);
  stats0_fin<<<1, 128>>>(part, g0, b0, fthr, fsgn);
  pack0_packw_kernel<<<4096 + 558, TB>>>(A, fthr, fsgn, P, wc1, wc2, wc3,
                                         wc4, wc5, Wp);

  // L1: 128->128 @32 +pool -> Cs
  bconv2_kernel<128, 128, 32, 32, 4, 1, 4, 16, true>
      <<<N * 8, TB>>>(P, Wp + 0, Cs);
  statsi_partial<<<dim3(128, 8), TB>>>(Cs, pll, 128, 256);
  statsi_fin<<<1, 128>>>(pll, g1, b1, fsc, fsf, thr, sgn, 128, 65536.0);
  pack_int_kernel<<<N * 256 * 4 / TB, TB>>>(Cs, thr, sgn, P, 128, 256, 4);

  // L2: 128->256 @16 -> As
  bconv2_kernel<256, 256, 16, 16, 4, 1, 4, 16, false>
      <<<N * 4, TB>>>(P, Wp + 4608, As);
  statsi_partial<<<dim3(256, 8), TB>>>(As, pll, 256, 256);
  statsi_fin<<<1, 256>>>(pll, g2, b2, fsc, fsf, thr, sgn, 256, 65536.0);
  pack_int_kernel<<<N * 256 * 8 / TB, TB>>>(As, thr, sgn, P, 256, 256, 8);

  // L3: 256->256 @16 +pool -> Cs
  bconv2_kernel<256, 128, 16, 16, 8, 2, 4, 16, true>
      <<<N * 8, TB>>>(P, Wp + 13824, Cs);
  statsi_partial<<<dim3(256, 8), TB>>>(Cs, pll, 256, 64);
  statsi_fin<<<1, 256>>>(pll, g3, b3, fsc, fsf, thr, sgn, 256, 16384.0);
  pack_int_kernel<<<N * 64 * 8 / TB, TB>>>(Cs, thr, sgn, P, 256, 64, 8);

  // L4: 256->512 @8 -> As
  bconv2_kernel<512, 128, 8, 8, 8, 2, 4, 8, false>
      <<<N * 8, TB>>>(P, Wp + 32256, As);
  statsi_partial<<<dim3(512, 8), TB>>>(As, pll, 512, 64);
  statsi_fin<<<2, 256>>>(pll, g4, b4, fsc, fsf, thr, sgn, 512, 16384.0);
  pack_int_kernel<<<N * 64 * 16 / TB, TB>>>(As, thr, sgn, P, 512, 64, 16);

  // L5: 512->512 @8 +pool -> Cs
  bconv2_kernel<512, 64, 8, 8, 16, 4, 4, 8, true>
      <<<N * 16, TB>>>(P, Wp + 69120, Cs);
  statsi_partial<<<dim3(512, 8), TB>>>(Cs, pll, 512, 16);
  statsi_fin<<<2, 256>>>(pll, g5, b5, fsc, fsf, thr, sgn, 512, 4096.0);

  // bn5 + hardtanh -> hbuf, then FC
  bn_ht_kernel<<<cdiv(2097152, TB), TB>>>(Cs, fsc, fsf, hbuf, 512, 16,
                                          2097152);
  fc_kernel<<<cdiv(N * 10 * 32, TB), TB>>>(hbuf, wfc, bfc, out);
}

// round 15
// speedup vs baseline: 2.0752x; 1.0381x over previous
#include <cuda_runtime.h>
#include <cstdint>
#include <math.h>

// ---------------------------------------------------------------------------
// VGG-small 1w1a forward, batch 256.  (R14 winner + bconv occupancy/ILP fix)
// conv0 fp32 -> stats0 (2-stage) -> pack0+packw ->
// [bconv popcount (sliding window, reg weights, 2 blocks/SM, split accum)
//  -> 2-stage int64 stats -> int pack] x5 -> bn+ht -> fc
// ---------------------------------------------------------------------------

__device__ __align__(16) float    g_A[33554432];   // conv0 fp32 / int16 NCHW
__device__ __align__(16) float    g_C[8388608];    // pooled int16 NCHW
__device__ __align__(16) uint32_t g_P[1048576];    // bitpacked act [n][y][x][NW]
__device__ __align__(16) uint32_t g_Wp[142848];    // bitpacked weights
__device__ double    g_part[8192];                 // stats0 partials
__device__ long long g_pll[16384];                 // int stats partials
__device__ float  g_fthr[512];
__device__ int    g_fsgn[512];
__device__ int    g_ithr[512];
__device__ int    g_isgn[512];
__device__ float  g_fsc[512];
__device__ float  g_fsf[512];

// ---------------- compensated fp32 helpers ---------------------------------
__device__ __forceinline__ void two_sum(float& s, float& c, float v) {
  float t = __fadd_rn(s, v);
  float z = __fsub_rn(t, s);
  float e = __fadd_rn(__fsub_rn(s, __fsub_rn(t, z)), __fsub_rn(v, z));
  s = t;
  c = __fadd_rn(c, e);
}

// ---------------- conv0: fp32 3->128, 32x32, pad 1 -------------------------
__global__ __launch_bounds__(256) void conv0_kernel(
    const float* __restrict__ x, const float* __restrict__ w,
    float* __restrict__ out) {
  __shared__ float sW[128 * 27];
  __shared__ float sX[3][3][34];
  int bx = blockIdx.x;
  int y = bx & 31, n = bx >> 5;
  int tid = threadIdx.x;
  for (int i = tid; i < 3456; i += 256) sW[i] = w[i];
  for (int i = tid; i < 3 * 3 * 34; i += 256) {
    int col = i % 34;
    int r = (i / 34) % 3;
    int ci = i / (34 * 3);
    int gy = y - 1 + r, gx = col - 1;
    float v = 0.f;
    if (gy >= 0 && gy < 32 && gx >= 0 && gx < 32)
      v = x[((n * 3 + ci) * 32 + gy) * 32 + gx];
    sX[ci][r][col] = v;
  }
  __syncthreads();
  int co = tid >> 1, xh = tid & 1, x0 = xh * 16;
  float wr[27];
#pragma unroll
  for (int ky = 0; ky < 3; ky++)
#pragma unroll
    for (int kx = 0; kx < 3; kx++)
#pragma unroll
      for (int ci = 0; ci < 3; ci++)
        wr[(ky * 3 + kx) * 3 + ci] = sW[((co * 3 + ci) * 3 + ky) * 3 + kx];
  float a[3][3][3];
#pragma unroll
  for (int r = 0; r < 3; r++)
#pragma unroll
    for (int ci = 0; ci < 3; ci++) {
      a[r][0][ci] = sX[ci][r][x0];
      a[r][1][ci] = sX[ci][r][x0 + 1];
    }
  float* obase = out + (((size_t)n * 128 + co) * 32 + y) * 32;
#pragma unroll
  for (int xi = 0; xi < 16; xi++) {
    int xc = x0 + xi;
#pragma unroll
    for (int r = 0; r < 3; r++)
#pragma unroll
      for (int ci = 0; ci < 3; ci++) a[r][2][ci] = sX[ci][r][xc + 2];
    float acc = 0.f;
#pragma unroll
    for (int ky = 0; ky < 3; ky++)
#pragma unroll
      for (int kx = 0; kx < 3; kx++)
#pragma unroll
        for (int ci = 0; ci < 3; ci++)
          acc = fmaf(a[ky][kx][ci], wr[(ky * 3 + kx) * 3 + ci], acc);
    obase[xc] = acc;
#pragma unroll
    for (int r = 0; r < 3; r++)
#pragma unroll
      for (int ci = 0; ci < 3; ci++) {
        a[r][0][ci] = a[r][1][ci];
        a[r][1][ci] = a[r][2][ci];
      }
  }
}

// ------- layer0 stats: 2-stage, comp-fp32 partials, fp64 combine -----------
__global__ __launch_bounds__(256) void stats0_partial(
    const float* __restrict__ x, double* __restrict__ part) {
  int c = blockIdx.x, ch = blockIdx.y;
  float s = 0.f, cs = 0.f, ss = 0.f, css = 0.f;
  for (int n = ch * 32; n < (ch + 1) * 32; n++) {
    const float* p = x + ((size_t)n * 128 + c) * 1024;
    for (int i = threadIdx.x; i < 1024; i += 256) {
      float v = p[i];
      two_sum(s, cs, v);
      float v2 = __fmul_rn(v, v);
      float e2 = __fmaf_rn(v, v, -v2);
      two_sum(ss, css, v2);
      css = __fadd_rn(css, e2);
    }
  }
  __shared__ double sh1[256], sh2[256];
  sh1[threadIdx.x] = (double)s + (double)cs;
  sh2[threadIdx.x] = (double)ss + (double)css;
  __syncthreads();
  for (int o = 128; o > 0; o >>= 1) {
    if (threadIdx.x < o) {
      sh1[threadIdx.x] += sh1[threadIdx.x + o];
      sh2[threadIdx.x] += sh2[threadIdx.x + o];
    }
    __syncthreads();
  }
  if (threadIdx.x == 0) {
    part[c * 8 + ch] = sh1[0];
    part[4096 + c * 8 + ch] = sh2[0];
  }
}

__global__ void stats0_fin(const double* __restrict__ part,
                           const float* __restrict__ g,
                           const float* __restrict__ b,
                           float* __restrict__ fthr, int* __restrict__ fsgn) {
  int c = blockIdx.x * blockDim.x + threadIdx.x;
  if (c >= 128) return;
  double S = 0.0, SS = 0.0;
  for (int ch = 0; ch < 8; ch++) {
    S += part[c * 8 + ch];
    SS += part[4096 + c * 8 + ch];
  }
  double cnt = 256.0 * 1024.0;
  double mean = S / cnt;
  double var = SS / cnt - mean * mean;
  double sc = (double)g[c] * rsqrt(var + 1e-5);
  double sf = (double)b[c] - mean * sc;
  if (sc > 0.0) {
    float v = (float)(-sf / sc);
    if (!isfinite(v)) v = 0.f;
    if (fma((double)v, sc, sf) >= 0.0) {
      for (int it = 0; it < 64; it++) {
        float d = nextafterf(v, -INFINITY);
        if (fma((double)d, sc, sf) >= 0.0) v = d; else break;
      }
    } else {
      for (int it = 0; it < 64; it++) {
        v = nextafterf(v, INFINITY);
        if (fma((double)v, sc, sf) >= 0.0) break;
      }
    }
    fthr[c] = v;
    fsgn[c] = 1;
  } else if (sc < 0.0) {
    float v = (float)(-sf / sc);
    if (!isfinite(v)) v = 0.f;
    if (fma((double)v, sc, sf) >= 0.0) {
      for (int it = 0; it < 64; it++) {
        float d = nextafterf(v, INFINITY);
        if (fma((double)d, sc, sf) >= 0.0) v = d; else break;
      }
    } else {
      for (int it = 0; it < 64; it++) {
        v = nextafterf(v, -INFINITY);
        if (fma((double)v, sc, sf) >= 0.0) break;
      }
    }
    fthr[c] = v;
    fsgn[c] = 0;
  } else {
    fthr[c] = (sf >= 0.0) ? -INFINITY : INFINITY;
    fsgn[c] = 1;
  }
}

// ------- fused: pack0 act bitpack + weight bitpack --------------------------
__global__ __launch_bounds__(256) void pack0_packw_kernel(
    const float* __restrict__ x, const float* __restrict__ fthr,
    const int* __restrict__ fsgn, uint32_t* __restrict__ apk,
    const float* __restrict__ w1, const float* __restrict__ w2,
    const float* __restrict__ w3, const float* __restrict__ w4,
    const float* __restrict__ w5, uint32_t* __restrict__ wpk) {
  const int R0 = 4096;
  int tid = threadIdx.x;
  int bx = blockIdx.x;
  if (bx < R0) {
    int gt = bx * 256 + tid;
    int lane = gt & 31;
    int gw = gt >> 5;
    int wrd = gw & 3;
    int pixel = (gw >> 2) * 32 + lane;
    int n = pixel >> 10, hw = pixel & 1023;
    const float* base = x + ((size_t)(n * 128 + wrd * 32)) * 1024 + hw;
    const float* tp = fthr + wrd * 32;
    const int* sp = fsgn + wrd * 32;
    uint32_t bits = 0;
#pragma unroll 8
    for (int k = 0; k < 32; k++) {
      float v = base[(size_t)k * 1024];
      bool bit = sp[k] ? (v >= tp[k]) : (v <= tp[k]);
      bits |= (bit ? 1u : 0u) << k;
    }
    apk[(size_t)pixel * 4 + wrd] = bits;
  } else {
    int idx = (bx - R0) * 256 + tid;
    if (idx >= 142848) return;
    const float* w;
    int Ci, l;
    if (idx < 4608) { w = w1; Ci = 128; l = idx; }
    else if (idx < 13824) { w = w2; Ci = 128; l = idx - 4608; }
    else if (idx < 32256) { w = w3; Ci = 256; l = idx - 13824; }
    else if (idx < 69120) { w = w4; Ci = 256; l = idx - 32256; }
    else { w = w5; Ci = 512; l = idx - 69120; }
    int NW = Ci >> 5;
    int wrd = l % NW;
    int t = l / NW;
    int tap = t % 9;
    int co = t / 9;
    uint32_t bits = 0;
#pragma unroll 8
    for (int k = 0; k < 32; k++) {
      float v = w[((size_t)co * Ci + (wrd * 32 + k)) * 9 + tap];
      bits |= (v >= 0.f ? 1u : 0u) << k;
    }
    wpk[idx] = bits;
  }
}

// ---- binary conv 3x3 pad 1: sliding window, reg weights, 2 blk/SM ---------
__device__ __forceinline__ int popc4(uint4 a, uint4 b) {
  return __popc(a.x ^ b.x) + __popc(a.y ^ b.y) +
         __popc(a.z ^ b.z) + __popc(a.w ^ b.w);
}

template <int CO, int CO_G, int H, int W, int NW, int SPLIT, int YT, int XT,
          bool POOL>
__global__ __launch_bounds__(CO_G* SPLIT*(W / XT), 2) void bconv2_kernel(
    const uint32_t* __restrict__ apk, const uint32_t* __restrict__ wpk,
    short* __restrict__ out) {
  constexpr int NTH = CO_G * SPLIT * (W / XT);
  constexpr int CGRP = CO / CO_G;
  __shared__ uint32_t sW[CO_G * 9 * NW];
  __shared__ uint32_t sA[(YT + 2) * W * NW];
  int bx = blockIdx.x;
  int cg = bx % CGRP;
  int yg = (bx / CGRP) % (H / YT);
  int n = bx / (CGRP * (H / YT));
  int tid = threadIdx.x;
  const uint4* wsrc =
      reinterpret_cast<const uint4*>(wpk + (size_t)cg * CO_G * 9 * NW);
  for (int i = tid; i < CO_G * 9 * NW / 4; i += NTH)
    reinterpret_cast<uint4*>(sW)[i] = wsrc[i];
  int ybase = yg * YT;
  constexpr int RW4 = W * NW / 4;
  for (int i = tid; i < (YT + 2) * RW4; i += NTH) {
    int r = i / RW4;
    int gy = ybase - 1 + r;
    uint4 v = make_uint4(0u, 0u, 0u, 0u);
    if (gy >= 0 && gy < H)
      v = reinterpret_cast<const uint4*>(
          apk + ((size_t)(n * H + gy) * W) * NW)[i % RW4];
    reinterpret_cast<uint4*>(sA)[i] = v;
  }
  __syncthreads();
  int slice = tid % SPLIT;
  int t2 = tid / SPLIT;
  int xg = t2 % (W / XT);
  int co_l = t2 / (W / XT);
  int x0 = xg * XT;
  uint4 wt[9];
#pragma unroll
  for (int t = 0; t < 9; t++)
    wt[t] = *reinterpret_cast<const uint4*>(
        &sW[(co_l * 9 + t) * NW + slice * 4]);
  int co = cg * CO_G + co_l;
  int pmax[XT / 2];
  int tmpv = 0;
#pragma unroll
  for (int ry = 0; ry < YT; ry++) {
    int y = ybase + ry;
    int rv0 = (y > 0) ? 1 : 0;
    int rv2 = (y < H - 1) ? 1 : 0;
    int nrows = 1 + rv0 + rv2;
    uint4 aL[3], aM[3], aR[3];
#pragma unroll
    for (int rr = 0; rr < 3; rr++) {
      aM[rr] = *reinterpret_cast<const uint4*>(
          &sA[((ry + rr) * W + x0) * NW + slice * 4]);
      aL[rr] = (x0 > 0)
                   ? *reinterpret_cast<const uint4*>(
                         &sA[((ry + rr) * W + x0 - 1) * NW + slice * 4])
                   : make_uint4(0u, 0u, 0u, 0u);
    }
#pragma unroll
    for (int xi = 0; xi < XT; xi++) {
      int xc = x0 + xi;
      int cl = (xc > 0) ? 1 : 0;
      int cr = (xc < W - 1) ? 1 : 0;
#pragma unroll
      for (int rr = 0; rr < 3; rr++)
        aR[rr] = cr ? *reinterpret_cast<const uint4*>(
                          &sA[((ry + rr) * W + xc + 1) * NW + slice * 4])
                    : make_uint4(0u, 0u, 0u, 0u);
      // split accumulators: one per kernel row, tree-combined (exact ints)
      int c0 = 0, c1 = 0, c2 = 0;
      if (rv0) {
        if (cl) c0 += popc4(aL[0], wt[0]);
        c0 += popc4(aM[0], wt[1]);
        if (cr) c0 += popc4(aR[0], wt[2]);
      }
      {
        if (cl) c1 += popc4(aL[1], wt[3]);
        c1 += popc4(aM[1], wt[4]);
        if (cr) c1 += popc4(aR[1], wt[5]);
      }
      if (rv2) {
        if (cl) c2 += popc4(aL[2], wt[6]);
        c2 += popc4(aM[2], wt[7]);
        if (cr) c2 += popc4(aR[2], wt[8]);
      }
      int cnt = (c0 + c1) + c2;
#pragma unroll
      for (int o = 1; o < SPLIT; o <<= 1)
        cnt += __shfl_xor_sync(0xffffffffu, cnt, o);
      int ncols = 1 + cl + cr;
      int val = nrows * ncols * 32 * NW - 2 * cnt;
      if (POOL) {
        if ((xi & 1) == 0) {
          tmpv = val;
        } else {
          int m2 = max(tmpv, val);
          if ((ry & 1) == 0) {
            pmax[xi >> 1] = m2;
          } else {
            int m = max(pmax[xi >> 1], m2);
            if (slice == 0)
              out[(((size_t)n * CO + co) * (H / 2) + (y >> 1)) * (W / 2) +
                  (xc >> 1)] = (short)m;
          }
        }
      } else {
        if (slice == 0)
          out[(((size_t)n * CO + co) * H + y) * W + xc] = (short)val;
      }
#pragma unroll
      for (int rr = 0; rr < 3; rr++) {
        aL[rr] = aM[rr];
        aM[rr] = aR[rr];
      }
    }
  }
}

// ------- binary-layer stats: 2-stage exact int64 ---------------------------
__global__ __launch_bounds__(256) void statsi_partial(
    const short* __restrict__ x, long long* __restrict__ pll,
    int C, int HW) {
  int c = blockIdx.x, ch = blockIdx.y;
  long long s = 0, ss = 0;
  for (int n = ch * 32; n < (ch + 1) * 32; n++) {
    const short* p = x + ((size_t)n * C + c) * HW;
    for (int i = threadIdx.x; i < HW; i += 256) {
      int v = p[i];
      s += v;
      ss += (long long)(v * v);
    }
  }
  __shared__ long long sh1[256], sh2[256];
  sh1[threadIdx.x] = s;
  sh2[threadIdx.x] = ss;
  __syncthreads();
  for (int o = 128; o > 0; o >>= 1) {
    if (threadIdx.x < o) {
      sh1[threadIdx.x] += sh1[threadIdx.x + o];
      sh2[threadIdx.x] += sh2[threadIdx.x + o];
    }
    __syncthreads();
  }
  if (threadIdx.x == 0) {
    pll[c * 8 + ch] = sh1[0];
    pll[8192 + c * 8 + ch] = sh2[0];
  }
}

__global__ void statsi_fin(const long long* __restrict__ pll,
                           const float* __restrict__ g,
                           const float* __restrict__ b,
                           float* __restrict__ fsc, float* __restrict__ fsf,
                           int* __restrict__ thr, int* __restrict__ sgn,
                           int C, double cnt) {
  int c = blockIdx.x * blockDim.x + threadIdx.x;
  if (c >= C) return;
  long long S = 0, SS = 0;
  for (int ch = 0; ch < 8; ch++) {
    S += pll[c * 8 + ch];
    SS += pll[8192 + c * 8 + ch];
  }
  double mean = (double)S / cnt;
  double var = (double)SS / cnt - mean * mean;
  double sc = (double)g[c] * rsqrt(var + 1e-5);
  double sf = (double)b[c] - mean * sc;
  fsc[c] = (float)sc;
  fsf[c] = (float)sf;
  double T = -sf / sc;
  if (sc > 0.0) {
    thr[c] = (int)ceil(T);
    sgn[c] = 1;
  } else {
    thr[c] = (int)floor(T);
    sgn[c] = 0;
  }
}

// -------- binary-layer pack: pure integer predicate ------------------------
__global__ __launch_bounds__(256) void pack_int_kernel(
    const short* __restrict__ x, const int* __restrict__ thr,
    const int* __restrict__ sgn, uint32_t* __restrict__ apk,
    int C, int HW, int NW) {
  int gt = blockIdx.x * 256 + threadIdx.x;
  int lane = gt & 31;
  int gw = gt >> 5;
  int wrd = gw % NW;
  int chunk = gw / NW;
  int pixel = chunk * 32 + lane;
  int n = pixel / HW, hw = pixel % HW;
  const short* base = x + ((size_t)n * C + wrd * 32) * HW + hw;
  const int* tp = thr + wrd * 32;
  const int* sp = sgn + wrd * 32;
  uint32_t bits = 0;
#pragma unroll 8
  for (int k = 0; k < 32; k++) {
    int v = base[(size_t)k * HW];
    bool bit = sp[k] ? (v >= tp[k]) : (v <= tp[k]);
    bits |= (bit ? 1u : 0u) << k;
  }
  apk[(size_t)pixel * NW + wrd] = bits;
}

// ------------- bn + hardtanh (fp32 continuous path) ------------------------
__global__ __launch_bounds__(256) void bn_ht_kernel(
    const short* __restrict__ in, const float* __restrict__ fsc,
    const float* __restrict__ fsf, float* __restrict__ out,
    int C, int HW, int total) {
  int idx = blockIdx.x * 256 + threadIdx.x;
  if (idx >= total) return;
  int c = (idx / HW) % C;
  float z = fmaf((float)in[idx], fsc[c], fsf[c]);
  out[idx] = fminf(1.f, fmaxf(-1.f, z));
}

// ----- FC: [256,8192] @ [10,8192]^T + b (TwoProd+Neumaier fp32) ------------
__global__ __launch_bounds__(256) void fc_kernel(
    const float* __restrict__ h, const float* __restrict__ wfc,
    const float* __restrict__ bfc, float* __restrict__ out) {
  int gtid = blockIdx.x * blockDim.x + threadIdx.x;
  int warp = gtid >> 5;
  int lane = gtid & 31;
  if (warp >= 256 * 10) return;
  int n = warp / 10, k = warp % 10;
  const float* hp = h + (size_t)n * 8192;
  const float* wp = wfc + (size_t)k * 8192;
  float s = 0.f, c = 0.f;
  for (int j = lane; j < 8192; j += 32) {
    float a = hp[j], b = wp[j];
    float p = __fmul_rn(a, b);
    float e = __fmaf_rn(a, b, -p);
    two_sum(s, c, p);
    c = __fadd_rn(c, e);
  }
  double d = (double)s + (double)c;
#pragma unroll
  for (int o = 16; o > 0; o >>= 1) d += __shfl_xor_sync(0xFFFFFFFFu, d, o);
  if (lane == 0) out[n * 10 + k] = (float)(d + (double)bfc[k]);
}

// ---------------------------------------------------------------------------
static inline int cdiv(int a, int b) { return (a + b - 1) / b; }

extern "C" void kernel_launch(void* const* d_in, const int* in_sizes, int n_in,
                              void* d_out, int out_size) {
  const float* x   = (const float*)d_in[0];
  const float* w0_ = (const float*)d_in[1];
  const float* g0  = (const float*)d_in[2];
  const float* b0  = (const float*)d_in[3];
  const float* wc1 = (const float*)d_in[4];
  const float* g1  = (const float*)d_in[5];
  const float* b1  = (const float*)d_in[6];
  const float* wc2 = (const float*)d_in[7];
  const float* g2  = (const float*)d_in[8];
  const float* b2  = (const float*)d_in[9];
  const float* wc3 = (const float*)d_in[10];
  const float* g3  = (const float*)d_in[11];
  const float* b3  = (const float*)d_in[12];
  const float* wc4 = (const float*)d_in[13];
  const float* g4  = (const float*)d_in[14];
  const float* b4  = (const float*)d_in[15];
  const float* wc5 = (const float*)d_in[16];
  const float* g5  = (const float*)d_in[17];
  const float* b5  = (const float*)d_in[18];
  const float* wfc = (const float*)d_in[19];
  const float* bfc = (const float*)d_in[20];
  float* out = (float*)d_out;

  float *A, *Cb, *fsc, *fsf, *fthr;
  uint32_t *P, *Wp;
  double* part;
  long long* pll;
  int *thr, *sgn, *fsgn;
  cudaGetSymbolAddress((void**)&A, g_A);
  cudaGetSymbolAddress((void**)&Cb, g_C);
  cudaGetSymbolAddress((void**)&P, g_P);
  cudaGetSymbolAddress((void**)&Wp, g_Wp);
  cudaGetSymbolAddress((void**)&part, g_part);
  cudaGetSymbolAddress((void**)&pll, g_pll);
  cudaGetSymbolAddress((void**)&fthr, g_fthr);
  cudaGetSymbolAddress((void**)&fsgn, g_fsgn);
  cudaGetSymbolAddress((void**)&thr, g_ithr);
  cudaGetSymbolAddress((void**)&sgn, g_isgn);
  cudaGetSymbolAddress((void**)&fsc, g_fsc);
  cudaGetSymbolAddress((void**)&fsf, g_fsf);
  short* As = (short*)A;
  short* Cs = (short*)Cb;
  float* hbuf = (float*)A;

  const int N = 256;
  const int TB = 256;

  conv0_kernel<<<N * 32, TB>>>(x, w0_, A);
  stats0_partial<<<dim3(128, 8), TB>>>(A, part);
  stats0_fin<<<1, 128>>>(part, g0, b0, fthr, fsgn);
  pack0_packw_kernel<<<4096 + 558, TB>>>(A, fthr, fsgn, P, wc1, wc2, wc3,
                                         wc4, wc5, Wp);

  // L1: 128->128 @32 +pool -> Cs
  bconv2_kernel<128, 128, 32, 32, 4, 1, 4, 16, true>
      <<<N * 8, TB>>>(P, Wp + 0, Cs);
  statsi_partial<<<dim3(128, 8), TB>>>(Cs, pll, 128, 256);
  statsi_fin<<<1, 128>>>(pll, g1, b1, fsc, fsf, thr, sgn, 128, 65536.0);
  pack_int_kernel<<<N * 256 * 4 / TB, TB>>>(Cs, thr, sgn, P, 128, 256, 4);

  // L2: 128->256 @16 -> As
  bconv2_kernel<256, 256, 16, 16, 4, 1, 4, 16, false>
      <<<N * 4, TB>>>(P, Wp + 4608, As);
  statsi_partial<<<dim3(256, 8), TB>>>(As, pll, 256, 256);
  statsi_fin<<<1, 256>>>(pll, g2, b2, fsc, fsf, thr, sgn, 256, 65536.0);
  pack_int_kernel<<<N * 256 * 8 / TB, TB>>>(As, thr, sgn, P, 256, 256, 8);

  // L3: 256->256 @16 +pool -> Cs
  bconv2_kernel<256, 128, 16, 16, 8, 2, 4, 16, true>
      <<<N * 8, TB>>>(P, Wp + 13824, Cs);
  statsi_partial<<<dim3(256, 8), TB>>>(Cs, pll, 256, 64);
  statsi_fin<<<1, 256>>>(pll, g3, b3, fsc, fsf, thr, sgn, 256, 16384.0);
  pack_int_kernel<<<N * 64 * 8 / TB, TB>>>(Cs, thr, sgn, P, 256, 64, 8);

  // L4: 256->512 @8 -> As
  bconv2_kernel<512, 128, 8, 8, 8, 2, 4, 8, false>
      <<<N * 8, TB>>>(P, Wp + 32256, As);
  statsi_partial<<<dim3(512, 8), TB>>>(As, pll, 512, 64);
  statsi_fin<<<2, 256>>>(pll, g4, b4, fsc, fsf, thr, sgn, 512, 16384.0);
  pack_int_kernel<<<N * 64 * 16 / TB, TB>>>(As, thr, sgn, P, 512, 64, 16);

  // L5: 512->512 @8 +pool -> Cs
  bconv2_kernel<512, 64, 8, 8, 16, 4, 4, 8, true>
      <<<N * 16, TB>>>(P, Wp + 69120, Cs);
  statsi_partial<<<dim3(512, 8), TB>>>(Cs, pll, 512, 16);
  statsi_fin<<<2, 256>>>(pll, g5, b5, fsc, fsf, thr, sgn, 512, 4096.0);

  // bn5 + hardtanh -> hbuf, then FC
  bn_ht_kernel<<<cdiv(2097152, TB), TB>>>(Cs, fsc, fsf, hbuf, 512, 16,
                                          2097152);
  fc_kernel<<<cdiv(N * 10 * 32, TB), TB>>>(hbuf, wfc, bfc, out);
}

// round 16
// speedup vs baseline: 2.0822x; 1.0034x over previous
#include <cuda_runtime.h>
#include <cstdint>
#include <math.h>

// ---------------------------------------------------------------------------
// VGG-small 1w1a forward, batch 256.
// conv0 fp32 -> stats0 (fused 2-stage, last-block fin) -> pack0+packw ->
// [bconv popcount uint2 slices (4 blocks/SM) -> 2-stage int64 stats ->
//  int pack] x5 -> bn+ht -> fc
// ---------------------------------------------------------------------------

__device__ __align__(16) float    g_A[33554432];   // conv0 fp32 / int16 NCHW
__device__ __align__(16) float    g_C[8388608];    // pooled int16 NCHW
__device__ __align__(16) uint32_t g_P[1048576];    // bitpacked act [n][y][x][NW]
__device__ __align__(16) uint32_t g_Wp[142848];    // bitpacked weights
__device__ double    g_part[8192];                 // stats0 partials
__device__ long long g_pll[16384];                 // int stats partials
__device__ int    g_cnt0 = 0;
__device__ float  g_fthr[512];
__device__ int    g_fsgn[512];
__device__ int    g_ithr[512];
__device__ int    g_isgn[512];
__device__ float  g_fsc[512];
__device__ float  g_fsf[512];

// ---------------- compensated fp32 helpers ---------------------------------
__device__ __forceinline__ void two_sum(float& s, float& c, float v) {
  float t = __fadd_rn(s, v);
  float z = __fsub_rn(t, s);
  float e = __fadd_rn(__fsub_rn(s, __fsub_rn(t, z)), __fsub_rn(v, z));
  s = t;
  c = __fadd_rn(c, e);
}

// ---------------- conv0: fp32 3->128, 32x32, pad 1 -------------------------
__global__ __launch_bounds__(256) void conv0_kernel(
    const float* __restrict__ x, const float* __restrict__ w,
    float* __restrict__ out) {
  __shared__ float sW[128 * 27];
  __shared__ float sX[3][3][34];
  int bx = blockIdx.x;
  int y = bx & 31, n = bx >> 5;
  int tid = threadIdx.x;
  for (int i = tid; i < 3456; i += 256) sW[i] = w[i];
  for (int i = tid; i < 3 * 3 * 34; i += 256) {
    int col = i % 34;
    int r = (i / 34) % 3;
    int ci = i / (34 * 3);
    int gy = y - 1 + r, gx = col - 1;
    float v = 0.f;
    if (gy >= 0 && gy < 32 && gx >= 0 && gx < 32)
      v = x[((n * 3 + ci) * 32 + gy) * 32 + gx];
    sX[ci][r][col] = v;
  }
  __syncthreads();
  int co = tid >> 1, xh = tid & 1, x0 = xh * 16;
  float wr[27];
#pragma unroll
  for (int ky = 0; ky < 3; ky++)
#pragma unroll
    for (int kx = 0; kx < 3; kx++)
#pragma unroll
      for (int ci = 0; ci < 3; ci++)
        wr[(ky * 3 + kx) * 3 + ci] = sW[((co * 3 + ci) * 3 + ky) * 3 + kx];
  float a[3][3][3];
#pragma unroll
  for (int r = 0; r < 3; r++)
#pragma unroll
    for (int ci = 0; ci < 3; ci++) {
      a[r][0][ci] = sX[ci][r][x0];
      a[r][1][ci] = sX[ci][r][x0 + 1];
    }
  float* obase = out + (((size_t)n * 128 + co) * 32 + y) * 32;
#pragma unroll
  for (int xi = 0; xi < 16; xi++) {
    int xc = x0 + xi;
#pragma unroll
    for (int r = 0; r < 3; r++)
#pragma unroll
      for (int ci = 0; ci < 3; ci++) a[r][2][ci] = sX[ci][r][xc + 2];
    float acc = 0.f;
#pragma unroll
    for (int ky = 0; ky < 3; ky++)
#pragma unroll
      for (int kx = 0; kx < 3; kx++)
#pragma unroll
        for (int ci = 0; ci < 3; ci++)
          acc = fmaf(a[ky][kx][ci], wr[(ky * 3 + kx) * 3 + ci], acc);
    obase[xc] = acc;
#pragma unroll
    for (int r = 0; r < 3; r++)
#pragma unroll
      for (int ci = 0; ci < 3; ci++) {
        a[r][0][ci] = a[r][1][ci];
        a[r][1][ci] = a[r][2][ci];
      }
  }
}

// ------- layer0 stats: fused 2-stage (last block finalizes) ----------------
__global__ __launch_bounds__(256) void stats0_fused(
    const float* __restrict__ x, const float* __restrict__ g,
    const float* __restrict__ b, double* __restrict__ part,
    float* __restrict__ fthr, int* __restrict__ fsgn) {
  int c = blockIdx.x, ch = blockIdx.y;
  int tid = threadIdx.x;
  float s = 0.f, cs = 0.f, ss = 0.f, css = 0.f;
  for (int n = ch * 32; n < (ch + 1) * 32; n++) {
    const float* p = x + ((size_t)n * 128 + c) * 1024;
    for (int i = tid; i < 1024; i += 256) {
      float v = p[i];
      two_sum(s, cs, v);
      float v2 = __fmul_rn(v, v);
      float e2 = __fmaf_rn(v, v, -v2);
      two_sum(ss, css, v2);
      css = __fadd_rn(css, e2);
    }
  }
  __shared__ double sh1[256], sh2[256];
  sh1[tid] = (double)s + (double)cs;
  sh2[tid] = (double)ss + (double)css;
  __syncthreads();
  for (int o = 128; o > 0; o >>= 1) {
    if (tid < o) {
      sh1[tid] += sh1[tid + o];
      sh2[tid] += sh2[tid + o];
    }
    __syncthreads();
  }
  __shared__ int isLast;
  if (tid == 0) {
    part[c * 8 + ch] = sh1[0];
    part[4096 + c * 8 + ch] = sh2[0];
    __threadfence();
    int t = atomicAdd(&g_cnt0, 1);
    isLast = (t == 128 * 8 - 1) ? 1 : 0;
  }
  __syncthreads();
  if (isLast) {
    if (tid < 128) {
      int cc = tid;
      double S = 0.0, SS = 0.0;
      for (int k = 0; k < 8; k++) {
        S += part[cc * 8 + k];
        SS += part[4096 + cc * 8 + k];
      }
      double cnt = 256.0 * 1024.0;
      double mean = S / cnt;
      double var = SS / cnt - mean * mean;
      double sc = (double)g[cc] * rsqrt(var + 1e-5);
      double sf = (double)b[cc] - mean * sc;
      if (sc > 0.0) {
        float v = (float)(-sf / sc);
        if (!isfinite(v)) v = 0.f;
        if (fma((double)v, sc, sf) >= 0.0) {
          for (int it = 0; it < 64; it++) {
            float d = nextafterf(v, -INFINITY);
            if (fma((double)d, sc, sf) >= 0.0) v = d; else break;
          }
        } else {
          for (int it = 0; it < 64; it++) {
            v = nextafterf(v, INFINITY);
            if (fma((double)v, sc, sf) >= 0.0) break;
          }
        }
        fthr[cc] = v;
        fsgn[cc] = 1;
      } else if (sc < 0.0) {
        float v = (float)(-sf / sc);
        if (!isfinite(v)) v = 0.f;
        if (fma((double)v, sc, sf) >= 0.0) {
          for (int it = 0; it < 64; it++) {
            float d = nextafterf(v, INFINITY);
            if (fma((double)d, sc, sf) >= 0.0) v = d; else break;
          }
        } else {
          for (int it = 0; it < 64; it++) {
            v = nextafterf(v, -INFINITY);
            if (fma((double)v, sc, sf) >= 0.0) break;
          }
        }
        fthr[cc] = v;
        fsgn[cc] = 0;
      } else {
        fthr[cc] = (sf >= 0.0) ? -INFINITY : INFINITY;
        fsgn[cc] = 1;
      }
    }
    if (tid == 0) g_cnt0 = 0;   // reset for next graph replay
  }
}

// ------- fused: pack0 act bitpack + weight bitpack --------------------------
__global__ __launch_bounds__(256) void pack0_packw_kernel(
    const float* __restrict__ x, const float* __restrict__ fthr,
    const int* __restrict__ fsgn, uint32_t* __restrict__ apk,
    const float* __restrict__ w1, const float* __restrict__ w2,
    const float* __restrict__ w3, const float* __restrict__ w4,
    const float* __restrict__ w5, uint32_t* __restrict__ wpk) {
  const int R0 = 4096;
  int tid = threadIdx.x;
  int bx = blockIdx.x;
  if (bx < R0) {
    int gt = bx * 256 + tid;
    int lane = gt & 31;
    int gw = gt >> 5;
    int wrd = gw & 3;
    int pixel = (gw >> 2) * 32 + lane;
    int n = pixel >> 10, hw = pixel & 1023;
    const float* base = x + ((size_t)(n * 128 + wrd * 32)) * 1024 + hw;
    const float* tp = fthr + wrd * 32;
    const int* sp = fsgn + wrd * 32;
    uint32_t bits = 0;
#pragma unroll 8
    for (int k = 0; k < 32; k++) {
      float v = base[(size_t)k * 1024];
      bool bit = sp[k] ? (v >= tp[k]) : (v <= tp[k]);
      bits |= (bit ? 1u : 0u) << k;
    }
    apk[(size_t)pixel * 4 + wrd] = bits;
  } else {
    int idx = (bx - R0) * 256 + tid;
    if (idx >= 142848) return;
    const float* w;
    int Ci, l;
    if (idx < 4608) { w = w1; Ci = 128; l = idx; }
    else if (idx < 13824) { w = w2; Ci = 128; l = idx - 4608; }
    else if (idx < 32256) { w = w3; Ci = 256; l = idx - 13824; }
    else if (idx < 69120) { w = w4; Ci = 256; l = idx - 32256; }
    else { w = w5; Ci = 512; l = idx - 69120; }
    int NW = Ci >> 5;
    int wrd = l % NW;
    int t = l / NW;
    int tap = t % 9;
    int co = t / 9;
    uint32_t bits = 0;
#pragma unroll 8
    for (int k = 0; k < 32; k++) {
      float v = w[((size_t)co * Ci + (wrd * 32 + k)) * 9 + tap];
      bits |= (v >= 0.f ? 1u : 0u) << k;
    }
    wpk[idx] = bits;
  }
}

// ---- binary conv 3x3 pad 1: uint2 slices, 4 blocks/SM ---------------------
__device__ __forceinline__ int popc2(uint2 a, uint2 b) {
  return __popc(a.x ^ b.x) + __popc(a.y ^ b.y);
}

template <int CO, int CO_G, int H, int W, int NW, int SPLIT, int YT, int XT,
          bool POOL>
__global__ __launch_bounds__(CO_G* SPLIT*(W / XT), 4) void bconv7_kernel(
    const uint32_t* __restrict__ apk, const uint32_t* __restrict__ wpk,
    short* __restrict__ out) {
  constexpr int NTH = CO_G * SPLIT * (W / XT);
  constexpr int CGRP = CO / CO_G;
  static_assert(NW / SPLIT == 2, "slice must be uint2");
  __shared__ uint32_t sW[CO_G * 9 * NW];
  __shared__ uint32_t sA[(YT + 2) * W * NW];
  int bx = blockIdx.x;
  int cg = bx % CGRP;
  int yg = (bx / CGRP) % (H / YT);
  int n = bx / (CGRP * (H / YT));
  int tid = threadIdx.x;
  const uint4* wsrc =
      reinterpret_cast<const uint4*>(wpk + (size_t)cg * CO_G * 9 * NW);
  for (int i = tid; i < CO_G * 9 * NW / 4; i += NTH)
    reinterpret_cast<uint4*>(sW)[i] = wsrc[i];
  int ybase = yg * YT;
  constexpr int RW4 = W * NW / 4;
  for (int i = tid; i < (YT + 2) * RW4; i += NTH) {
    int r = i / RW4;
    int gy = ybase - 1 + r;
    uint4 v = make_uint4(0u, 0u, 0u, 0u);
    if (gy >= 0 && gy < H)
      v = reinterpret_cast<const uint4*>(
          apk + ((size_t)(n * H + gy) * W) * NW)[i % RW4];
    reinterpret_cast<uint4*>(sA)[i] = v;
  }
  __syncthreads();
  int slice = tid % SPLIT;
  int t2 = tid / SPLIT;
  int xg = t2 % (W / XT);
  int co_l = t2 / (W / XT);
  int x0 = xg * XT;
  uint2 wt[9];
#pragma unroll
  for (int t = 0; t < 9; t++)
    wt[t] = *reinterpret_cast<const uint2*>(
        &sW[(co_l * 9 + t) * NW + slice * 2]);
  int co = cg * CO_G + co_l;
  int pmax[XT / 2];
  int tmpv = 0;
#pragma unroll
  for (int ry = 0; ry < YT; ry++) {
    int y = ybase + ry;
    int rv0 = (y > 0) ? 1 : 0;
    int rv2 = (y < H - 1) ? 1 : 0;
    int nrows = 1 + rv0 + rv2;
    uint2 aL[3], aM[3], aR[3];
#pragma unroll
    for (int rr = 0; rr < 3; rr++) {
      aM[rr] = *reinterpret_cast<const uint2*>(
          &sA[((ry + rr) * W + x0) * NW + slice * 2]);
      aL[rr] = (x0 > 0)
                   ? *reinterpret_cast<const uint2*>(
                         &sA[((ry + rr) * W + x0 - 1) * NW + slice * 2])
                   : make_uint2(0u, 0u);
    }
#pragma unroll
    for (int xi = 0; xi < XT; xi++) {
      int xc = x0 + xi;
      int cl = (xc > 0) ? 1 : 0;
      int cr = (xc < W - 1) ? 1 : 0;
#pragma unroll
      for (int rr = 0; rr < 3; rr++)
        aR[rr] = cr ? *reinterpret_cast<const uint2*>(
                          &sA[((ry + rr) * W + xc + 1) * NW + slice * 2])
                    : make_uint2(0u, 0u);
      int c0 = 0, c1 = 0, c2 = 0;
      if (rv0) {
        if (cl) c0 += popc2(aL[0], wt[0]);
        c0 += popc2(aM[0], wt[1]);
        if (cr) c0 += popc2(aR[0], wt[2]);
      }
      {
        if (cl) c1 += popc2(aL[1], wt[3]);
        c1 += popc2(aM[1], wt[4]);
        if (cr) c1 += popc2(aR[1], wt[5]);
      }
      if (rv2) {
        if (cl) c2 += popc2(aL[2], wt[6]);
        c2 += popc2(aM[2], wt[7]);
        if (cr) c2 += popc2(aR[2], wt[8]);
      }
      int cnt = (c0 + c1) + c2;
#pragma unroll
      for (int o = 1; o < SPLIT; o <<= 1)
        cnt += __shfl_xor_sync(0xffffffffu, cnt, o);
      int ncols = 1 + cl + cr;
      int val = nrows * ncols * 32 * NW - 2 * cnt;
      if (POOL) {
        if ((xi & 1) == 0) {
          tmpv = val;
        } else {
          int m2 = max(tmpv, val);
          if ((ry & 1) == 0) {
            pmax[xi >> 1] = m2;
          } else {
            int m = max(pmax[xi >> 1], m2);
            if (slice == 0)
              out[(((size_t)n * CO + co) * (H / 2) + (y >> 1)) * (W / 2) +
                  (xc >> 1)] = (short)m;
          }
        }
      } else {
        if (slice == 0)
          out[(((size_t)n * CO + co) * H + y) * W + xc] = (short)val;
      }
#pragma unroll
      for (int rr = 0; rr < 3; rr++) {
        aL[rr] = aM[rr];
        aM[rr] = aR[rr];
      }
    }
  }
}

// ------- binary-layer stats: 2-stage exact int64 ---------------------------
__global__ __launch_bounds__(256) void statsi_partial(
    const short* __restrict__ x, long long* __restrict__ pll,
    int C, int HW) {
  int c = blockIdx.x, ch = blockIdx.y;
  long long s = 0, ss = 0;
  for (int n = ch * 32; n < (ch + 1) * 32; n++) {
    const short* p = x + ((size_t)n * C + c) * HW;
    for (int i = threadIdx.x; i < HW; i += 256) {
      int v = p[i];
      s += v;
      ss += (long long)(v * v);
    }
  }
  __shared__ long long sh1[256], sh2[256];
  sh1[threadIdx.x] = s;
  sh2[threadIdx.x] = ss;
  __syncthreads();
  for (int o = 128; o > 0; o >>= 1) {
    if (threadIdx.x < o) {
      sh1[threadIdx.x] += sh1[threadIdx.x + o];
      sh2[threadIdx.x] += sh2[threadIdx.x + o];
    }
    __syncthreads();
  }
  if (threadIdx.x == 0) {
    pll[c * 8 + ch] = sh1[0];
    pll[8192 + c * 8 + ch] = sh2[0];
  }
}

__global__ void statsi_fin(const long long* __restrict__ pll,
                           const float* __restrict__ g,
                           const float* __restrict__ b,
                           float* __restrict__ fsc, float* __restrict__ fsf,
                           int* __restrict__ thr, int* __restrict__ sgn,
                           int C, double cnt) {
  int c = blockIdx.x * blockDim.x + threadIdx.x;
  if (c >= C) return;
  long long S = 0, SS = 0;
  for (int ch = 0; ch < 8; ch++) {
    S += pll[c * 8 + ch];
    SS += pll[8192 + c * 8 + ch];
  }
  double mean = (double)S / cnt;
  double var = (double)SS / cnt - mean * mean;
  double sc = (double)g[c] * rsqrt(var + 1e-5);
  double sf = (double)b[c] - mean * sc;
  fsc[c] = (float)sc;
  fsf[c] = (float)sf;
  double T = -sf / sc;
  if (sc > 0.0) {
    thr[c] = (int)ceil(T);
    sgn[c] = 1;
  } else {
    thr[c] = (int)floor(T);
    sgn[c] = 0;
  }
}

// -------- binary-layer pack: pure integer predicate ------------------------
__global__ __launch_bounds__(256) void pack_int_kernel(
    const short* __restrict__ x, const int* __restrict__ thr,
    const int* __restrict__ sgn, uint32_t* __restrict__ apk,
    int C, int HW, int NW) {
  int gt = blockIdx.x * 256 + threadIdx.x;
  int lane = gt & 31;
  int gw = gt >> 5;
  int wrd = gw % NW;
  int chunk = gw / NW;
  int pixel = chunk * 32 + lane;
  int n = pixel / HW, hw = pixel % HW;
  const short* base = x + ((size_t)n * C + wrd * 32) * HW + hw;
  const int* tp = thr + wrd * 32;
  const int* sp = sgn + wrd * 32;
  uint32_t bits = 0;
#pragma unroll 8
  for (int k = 0; k < 32; k++) {
    int v = base[(size_t)k * HW];
    bool bit = sp[k] ? (v >= tp[k]) : (v <= tp[k]);
    bits |= (bit ? 1u : 0u) << k;
  }
  apk[(size_t)pixel * NW + wrd] = bits;
}

// ------------- bn + hardtanh (fp32 continuous path) ------------------------
__global__ __launch_bounds__(256) void bn_ht_kernel(
    const short* __restrict__ in, const float* __restrict__ fsc,
    const float* __restrict__ fsf, float* __restrict__ out,
    int C, int HW, int total) {
  int idx = blockIdx.x * 256 + threadIdx.x;
  if (idx >= total) return;
  int c = (idx / HW) % C;
  float z = fmaf((float)in[idx], fsc[c], fsf[c]);
  out[idx] = fminf(1.f, fmaxf(-1.f, z));
}

// ----- FC: [256,8192] @ [10,8192]^T + b (TwoProd+Neumaier fp32) ------------
__global__ __launch_bounds__(256) void fc_kernel(
    const float* __restrict__ h, const float* __restrict__ wfc,
    const float* __restrict__ bfc, float* __restrict__ out) {
  int gtid = blockIdx.x * blockDim.x + threadIdx.x;
  int warp = gtid >> 5;
  int lane = gtid & 31;
  if (warp >= 256 * 10) return;
  int n = warp / 10, k = warp % 10;
  const float* hp = h + (size_t)n * 8192;
  const float* wp = wfc + (size_t)k * 8192;
  float s = 0.f, c = 0.f;
  for (int j = lane; j < 8192; j += 32) {
    float a = hp[j], b = wp[j];
    float p = __fmul_rn(a, b);
    float e = __fmaf_rn(a, b, -p);
    two_sum(s, c, p);
    c = __fadd_rn(c, e);
  }
  double d = (double)s + (double)c;
#pragma unroll
  for (int o = 16; o > 0; o >>= 1) d += __shfl_xor_sync(0xFFFFFFFFu, d, o);
  if (lane == 0) out[n * 10 + k] = (float)(d + (double)bfc[k]);
}

// ---------------------------------------------------------------------------
static inline int cdiv(int a, int b) { return (a + b - 1) / b; }

extern "C" void kernel_launch(void* const* d_in, const int* in_sizes, int n_in,
                              void* d_out, int out_size) {
  const float* x   = (const float*)d_in[0];
  const float* w0_ = (const float*)d_in[1];
  const float* g0  = (const float*)d_in[2];
  const float* b0  = (const float*)d_in[3];
  const float* wc1 = (const float*)d_in[4];
  const float* g1  = (const float*)d_in[5];
  const float* b1  = (const float*)d_in[6];
  const float* wc2 = (const float*)d_in[7];
  const float* g2  = (const float*)d_in[8];
  const float* b2  = (const float*)d_in[9];
  const float* wc3 = (const float*)d_in[10];
  const float* g3  = (const float*)d_in[11];
  const float* b3  = (const float*)d_in[12];
  const float* wc4 = (const float*)d_in[13];
  const float* g4  = (const float*)d_in[14];
  const float* b4  = (const float*)d_in[15];
  const float* wc5 = (const float*)d_in[16];
  const float* g5  = (const float*)d_in[17];
  const float* b5  = (const float*)d_in[18];
  const float* wfc = (const float*)d_in[19];
  const float* bfc = (const float*)d_in[20];
  float* out = (float*)d_out;

  float *A, *Cb, *fsc, *fsf, *fthr;
  uint32_t *P, *Wp;
  double* part;
  long long* pll;
  int *thr, *sgn, *fsgn;
  cudaGetSymbolAddress((void**)&A, g_A);
  cudaGetSymbolAddress((void**)&Cb, g_C);
  cudaGetSymbolAddress((void**)&P, g_P);
  cudaGetSymbolAddress((void**)&Wp, g_Wp);
  cudaGetSymbolAddress((void**)&part, g_part);
  cudaGetSymbolAddress((void**)&pll, g_pll);
  cudaGetSymbolAddress((void**)&fthr, g_fthr);
  cudaGetSymbolAddress((void**)&fsgn, g_fsgn);
  cudaGetSymbolAddress((void**)&thr, g_ithr);
  cudaGetSymbolAddress((void**)&sgn, g_isgn);
  cudaGetSymbolAddress((void**)&fsc, g_fsc);
  cudaGetSymbolAddress((void**)&fsf, g_fsf);
  short* As = (short*)A;
  short* Cs = (short*)Cb;
  float* hbuf = (float*)A;

  const int N = 256;
  const int TB = 256;

  // 0: conv0; 1: stats0_fused; 2: pack0+packw; 3: bconv L1 (profiled slot)
  conv0_kernel<<<N * 32, TB>>>(x, w0_, A);
  stats0_fused<<<dim3(128, 8), TB>>>(A, g0, b0, part, fthr, fsgn);
  pack0_packw_kernel<<<4096 + 558, TB>>>(A, fthr, fsgn, P, wc1, wc2, wc3,
                                         wc4, wc5, Wp);

  // L1: 128->128 @32 +pool -> Cs
  bconv7_kernel<128, 64, 32, 32, 4, 2, 4, 16, true>
      <<<N * 2 * 8, TB>>>(P, Wp + 0, Cs);
  statsi_partial<<<dim3(128, 8), TB>>>(Cs, pll, 128, 256);
  statsi_fin<<<1, 128>>>(pll, g1, b1, fsc, fsf, thr, sgn, 128, 65536.0);
  pack_int_kernel<<<N * 256 * 4 / TB, TB>>>(Cs, thr, sgn, P, 128, 256, 4);

  // L2: 128->256 @16 -> As
  bconv7_kernel<256, 128, 16, 16, 4, 2, 4, 16, false>
      <<<N * 2 * 4, TB>>>(P, Wp + 4608, As);
  statsi_partial<<<dim3(256, 8), TB>>>(As, pll, 256, 256);
  statsi_fin<<<1, 256>>>(pll, g2, b2, fsc, fsf, thr, sgn, 256, 65536.0);
  pack_int_kernel<<<N * 256 * 8 / TB, TB>>>(As, thr, sgn, P, 256, 256, 8);

  // L3: 256->256 @16 +pool -> Cs
  bconv7_kernel<256, 64, 16, 16, 8, 4, 4, 16, true>
      <<<N * 4 * 4, TB>>>(P, Wp + 13824, Cs);
  statsi_partial<<<dim3(256, 8), TB>>>(Cs, pll, 256, 64);
  statsi_fin<<<1, 256>>>(pll, g3, b3, fsc, fsf, thr, sgn, 256, 16384.0);
  pack_int_kernel<<<N * 64 * 8 / TB, TB>>>(Cs, thr, sgn, P, 256, 64, 8);

  // L4: 256->512 @8 -> As
  bconv7_kernel<512, 64, 8, 8, 8, 4, 4, 8, false>
      <<<N * 8 * 2, TB>>>(P, Wp + 32256, As);
  statsi_partial<<<dim3(512, 8), TB>>>(As, pll, 512, 64);
  statsi_fin<<<2, 256>>>(pll, g4, b4, fsc, fsf, thr, sgn, 512, 16384.0);
  pack_int_kernel<<<N * 64 * 16 / TB, TB>>>(As, thr, sgn, P, 512, 64, 16);

  // L5: 512->512 @8 +pool -> Cs
  bconv7_kernel<512, 32, 8, 8, 16, 8, 4, 8, true>
      <<<N * 16 * 2, TB>>>(P, Wp + 69120, Cs);
  statsi_partial<<<dim3(512, 8), TB>>>(Cs, pll, 512, 16);
  statsi_fin<<<2, 256>>>(pll, g5, b5, fsc, fsf, thr, sgn, 512, 4096.0);

  // bn5 + hardtanh -> hbuf, then FC
  bn_ht_kernel<<<cdiv(2097152, TB), TB>>>(Cs, fsc, fsf, hbuf, 512, 16,
                                          2097152);
  fc_kernel<<<cdiv(N * 10 * 32, TB), TB>>>(hbuf, wfc, bfc, out);
}